// round 1
// baseline (speedup 1.0000x reference)
#include <cuda_runtime.h>
#include <cuda_bf16.h>
#include <cstdint>

// Problem constants
#define Bv     4
#define Nseq   8192
#define EMBED  1024
#define HEADS  16
#define HDIM   64
#define RANK   512
#define MTOK   (Bv * Nseq)          // 32768 rows

// ---------------------------------------------------------------------------
// Scratch buffers (__device__ globals; allocation is forbidden)
// ---------------------------------------------------------------------------
__device__ float g_Y1[MTOK * RANK];          // low-rank intermediate (reused q/k/v)
__device__ float g_Q[MTOK * EMBED];          // elu(q)+1
__device__ float g_K[MTOK * EMBED];          // elu(k)+1
__device__ float g_V[MTOK * EMBED];          // v
__device__ float g_attn[MTOK * EMBED];       // attention output (pre-Wo)
__device__ float g_kvks[Bv * HEADS * (HDIM * HDIM + HDIM)]; // kv[64][64][64] then ksum[64][64]

#define KV_ELEMS   (Bv * HEADS * HDIM * HDIM)   // 262144
#define KS_ELEMS   (Bv * HEADS * HDIM)          // 4096

// ---------------------------------------------------------------------------
// Tiled fp32 NT GEMM: C[m,n] = sum_k A[m,k] * B[n,k]  (+ epilogue)
// A: [M,K] row-major, B: [N,K] row-major. M%128==0, N%128==0, K%16==0.
// MODE 0: C = acc
// MODE 1: C = elu(acc + bias[n]) + 1   (== acc+bias+1 if >0 else exp(acc+bias))
// MODE 2: C = acc + bias[n]
// ---------------------------------------------------------------------------
#define BM 128
#define BN 128
#define BK 16
#define TM 8
#define TN 8

template <int MODE>
__global__ __launch_bounds__(256, 2) void sgemm_nt(
    const float* __restrict__ A, const float* __restrict__ B,
    const float* __restrict__ bias, float* __restrict__ C,
    int M, int N, int K)
{
    __shared__ float As[BK][BM + 4];
    __shared__ float Bs[BK][BN + 4];

    const int bn = blockIdx.x;
    const int bm = blockIdx.y;
    const int tid = threadIdx.x;
    const int tr = tid >> 4;          // 0..15
    const int tc = tid & 15;          // 0..15

    const float* Ab = A + (size_t)bm * BM * K;
    const float* Bb = B + (size_t)bn * BN * K;

    const int lr = tid >> 2;          // 0..63
    const int lc = (tid & 3) * 4;     // 0,4,8,12

    float acc[TM][TN];
#pragma unroll
    for (int i = 0; i < TM; ++i)
#pragma unroll
        for (int j = 0; j < TN; ++j) acc[i][j] = 0.f;

    for (int k0 = 0; k0 < K; k0 += BK) {
#pragma unroll
        for (int h = 0; h < 2; ++h) {
            const int row = lr + h * 64;
            float4 va = *reinterpret_cast<const float4*>(Ab + (size_t)row * K + k0 + lc);
            As[lc + 0][row] = va.x; As[lc + 1][row] = va.y;
            As[lc + 2][row] = va.z; As[lc + 3][row] = va.w;
            float4 vb = *reinterpret_cast<const float4*>(Bb + (size_t)row * K + k0 + lc);
            Bs[lc + 0][row] = vb.x; Bs[lc + 1][row] = vb.y;
            Bs[lc + 2][row] = vb.z; Bs[lc + 3][row] = vb.w;
        }
        __syncthreads();

#pragma unroll
        for (int k = 0; k < BK; ++k) {
            float4 a0 = *reinterpret_cast<const float4*>(&As[k][tr * TM]);
            float4 a1 = *reinterpret_cast<const float4*>(&As[k][tr * TM + 4]);
            float4 b0 = *reinterpret_cast<const float4*>(&Bs[k][tc * TN]);
            float4 b1 = *reinterpret_cast<const float4*>(&Bs[k][tc * TN + 4]);
            float ra[TM] = {a0.x, a0.y, a0.z, a0.w, a1.x, a1.y, a1.z, a1.w};
            float rb[TN] = {b0.x, b0.y, b0.z, b0.w, b1.x, b1.y, b1.z, b1.w};
#pragma unroll
            for (int i = 0; i < TM; ++i)
#pragma unroll
                for (int j = 0; j < TN; ++j)
                    acc[i][j] = fmaf(ra[i], rb[j], acc[i][j]);
        }
        __syncthreads();
    }

    // epilogue
    float bvals[TN];
    if (MODE >= 1) {
#pragma unroll
        for (int j = 0; j < TN; ++j)
            bvals[j] = __ldg(bias + bn * BN + tc * TN + j);
    }
#pragma unroll
    for (int i = 0; i < TM; ++i) {
        const int m = bm * BM + tr * TM + i;
        float* Cp = C + (size_t)m * N + bn * BN + tc * TN;
#pragma unroll
        for (int j = 0; j < TN; ++j) {
            float v = acc[i][j];
            if (MODE >= 1) v += bvals[j];
            if (MODE == 1) v = (v > 0.f) ? (v + 1.f) : __expf(v);
            Cp[j] = v;
        }
    }
}

// ---------------------------------------------------------------------------
// zero kernel for kv/ksum accumulators (must run each replay)
// ---------------------------------------------------------------------------
__global__ void zero_kernel(float* __restrict__ p, int n)
{
    int i = blockIdx.x * blockDim.x + threadIdx.x;
    if (i < n) p[i] = 0.f;
}

// ---------------------------------------------------------------------------
// kv[bh][d][e] = sum_n k[bh][n][d] * v[bh][n][e];  ksum[bh][d] = sum_n k
// grid: (B*H, chunks). Each block reduces CH rows, atomicAdd into global.
// ---------------------------------------------------------------------------
#define KV_CH 512

__global__ __launch_bounds__(256) void kv_ksum_kernel(
    const float* __restrict__ Km, const float* __restrict__ Vm,
    float* __restrict__ kv, float* __restrict__ ksum)
{
    const int bh = blockIdx.x;            // 0..63
    const int b = bh >> 4, h = bh & 15;
    const int chunk = blockIdx.y;
    const int tid = threadIdx.x;

    __shared__ float sk[8][64];
    __shared__ float sv[8][64];

    const int d  = tid >> 2;              // 0..63
    const int e0 = (tid & 3) * 16;        // 0,16,32,48

    float acc[16];
#pragma unroll
    for (int j = 0; j < 16; ++j) acc[j] = 0.f;
    float ks = 0.f;

    const size_t base = ((size_t)b * Nseq + (size_t)chunk * KV_CH) * EMBED + h * HDIM;

    const int r0 = tid >> 6, c0 = tid & 63;          // first 256 elems
    const int r1 = (tid + 256) >> 6, c1 = tid & 63;  // second 256 elems

    for (int p = 0; p < KV_CH / 8; ++p) {
        const size_t rb = base + (size_t)p * 8 * EMBED;
        sk[r0][c0] = Km[rb + (size_t)r0 * EMBED + c0];
        sk[r1][c1] = Km[rb + (size_t)r1 * EMBED + c1];
        sv[r0][c0] = Vm[rb + (size_t)r0 * EMBED + c0];
        sv[r1][c1] = Vm[rb + (size_t)r1 * EMBED + c1];
        __syncthreads();
#pragma unroll
        for (int r = 0; r < 8; ++r) {
            const float kd = sk[r][d];
            ks += kd;
#pragma unroll
            for (int j = 0; j < 16; ++j)
                acc[j] = fmaf(kd, sv[r][e0 + j], acc[j]);
        }
        __syncthreads();
    }

    float* kvp = kv + (size_t)bh * (HDIM * HDIM) + d * HDIM + e0;
#pragma unroll
    for (int j = 0; j < 16; ++j) atomicAdd(kvp + j, acc[j]);
    if ((tid & 3) == 0) atomicAdd(ksum + bh * HDIM + d, ks);
}

// ---------------------------------------------------------------------------
// attn[b,n,h*64+e] = (sum_d q[d]*kv[d][e]) / (sum_d q[d]*ksum[d] + 1e-6)
// grid: (B*H, N/128). 256 threads; 2 threads per token (32 e-values each).
// ---------------------------------------------------------------------------
__global__ __launch_bounds__(256) void attn_kernel(
    const float* __restrict__ Qm, const float* __restrict__ kv,
    const float* __restrict__ ksum, float* __restrict__ out)
{
    const int bh = blockIdx.x;
    const int b = bh >> 4, h = bh & 15;
    const int nt = blockIdx.y;            // token chunk of 128
    const int tid = threadIdx.x;

    __shared__ float kv_s[64][65];
    __shared__ float ks_s[64];
    __shared__ float q_s[128][65];

    for (int i = tid; i < 4096; i += 256)
        kv_s[i >> 6][i & 63] = kv[(size_t)bh * 4096 + i];
    if (tid < 64) ks_s[tid] = ksum[bh * 64 + tid];

    const size_t base = ((size_t)b * Nseq + (size_t)nt * 128) * EMBED + h * HDIM;
    for (int i = tid; i < 128 * 64; i += 256) {
        const int r = i >> 6, c = i & 63;
        q_s[r][c] = Qm[base + (size_t)r * EMBED + c];
    }
    __syncthreads();

    const int t  = tid >> 1;              // token 0..127
    const int e0 = (tid & 1) * 32;

    float denom = 0.f;
#pragma unroll
    for (int d2 = 0; d2 < 64; ++d2)
        denom = fmaf(q_s[t][d2], ks_s[d2], denom);
    denom += 1e-6f;

    float acc[32];
#pragma unroll
    for (int j = 0; j < 32; ++j) acc[j] = 0.f;
#pragma unroll 4
    for (int d2 = 0; d2 < 64; ++d2) {
        const float qd = q_s[t][d2];
#pragma unroll
        for (int j = 0; j < 32; ++j)
            acc[j] = fmaf(qd, kv_s[d2][e0 + j], acc[j]);
    }

    const float inv = 1.0f / denom;
    float* op = out + base + (size_t)t * EMBED + e0;
#pragma unroll
    for (int j = 0; j < 32; ++j) op[j] = acc[j] * inv;
}

// ---------------------------------------------------------------------------
// launch
// ---------------------------------------------------------------------------
extern "C" void kernel_launch(void* const* d_in, const int* in_sizes, int n_in,
                              void* d_out, int out_size)
{
    const float* query   = (const float*)d_in[0];
    const float* key_    = (const float*)d_in[1];
    const float* value   = (const float*)d_in[2];
    const float* Wq_down = (const float*)d_in[3];
    const float* Wq_up   = (const float*)d_in[4];
    const float* bq_up   = (const float*)d_in[5];
    const float* Wk_down = (const float*)d_in[6];
    const float* Wk_up   = (const float*)d_in[7];
    const float* bk_up   = (const float*)d_in[8];
    const float* Wv_down = (const float*)d_in[9];
    const float* Wv_up   = (const float*)d_in[10];
    const float* bv_up   = (const float*)d_in[11];
    const float* Wo      = (const float*)d_in[12];
    const float* bo      = (const float*)d_in[13];
    float* out = (float*)d_out;

    float *Y1, *Q, *K, *V, *Attn, *KVKS;
    cudaGetSymbolAddress((void**)&Y1,   g_Y1);
    cudaGetSymbolAddress((void**)&Q,    g_Q);
    cudaGetSymbolAddress((void**)&K,    g_K);
    cudaGetSymbolAddress((void**)&V,    g_V);
    cudaGetSymbolAddress((void**)&Attn, g_attn);
    cudaGetSymbolAddress((void**)&KVKS, g_kvks);
    float* KV = KVKS;
    float* KS = KVKS + KV_ELEMS;

    const dim3 blk(256);
    const dim3 grid_down(RANK / BN, MTOK / BM);    // N=512
    const dim3 grid_up(EMBED / BN, MTOK / BM);     // N=1024

    // Q path
    sgemm_nt<0><<<grid_down, blk>>>(query, Wq_down, nullptr, Y1, MTOK, RANK, EMBED);
    sgemm_nt<1><<<grid_up,   blk>>>(Y1, Wq_up, bq_up, Q, MTOK, EMBED, RANK);
    // K path
    sgemm_nt<0><<<grid_down, blk>>>(key_, Wk_down, nullptr, Y1, MTOK, RANK, EMBED);
    sgemm_nt<1><<<grid_up,   blk>>>(Y1, Wk_up, bk_up, K, MTOK, EMBED, RANK);
    // V path
    sgemm_nt<0><<<grid_down, blk>>>(value, Wv_down, nullptr, Y1, MTOK, RANK, EMBED);
    sgemm_nt<2><<<grid_up,   blk>>>(Y1, Wv_up, bv_up, V, MTOK, EMBED, RANK);

    // kv / ksum reduction
    const int nz = KV_ELEMS + KS_ELEMS;
    zero_kernel<<<(nz + 255) / 256, 256>>>(KVKS, nz);
    kv_ksum_kernel<<<dim3(Bv * HEADS, Nseq / KV_CH), blk>>>(K, V, KV, KS);

    // numerator / denominator
    attn_kernel<<<dim3(Bv * HEADS, Nseq / 128), blk>>>(Q, KV, KS, Attn);

    // output projection
    sgemm_nt<2><<<grid_up, blk>>>(Attn, Wo, bo, out, MTOK, EMBED, EMBED);
}

// round 5
// speedup vs baseline: 1.9782x; 1.9782x over previous
#include <cuda_runtime.h>
#include <cuda_bf16.h>
#include <cstdint>

// ---------------------------------------------------------------------------
// Problem constants
// ---------------------------------------------------------------------------
#define Bv     4
#define Nseq   8192
#define EMBED  1024
#define HEADS  16
#define HDIM   64
#define RANK   512
#define MTOK   (Bv * Nseq)          // 32768

// ---------------------------------------------------------------------------
// Scratch (__device__ globals; allocation forbidden)
// ---------------------------------------------------------------------------
__device__ __nv_bfloat16 g_inHi[MTOK * EMBED];
__device__ __nv_bfloat16 g_inLo[MTOK * EMBED];
__device__ __nv_bfloat16 g_yHi [MTOK * RANK];
__device__ __nv_bfloat16 g_yLo [MTOK * RANK];
__device__ __nv_bfloat16 g_atHi[MTOK * EMBED];
__device__ __nv_bfloat16 g_atLo[MTOK * EMBED];

#define W_QD 0
#define W_QU (W_QD + RANK*EMBED)
#define W_KD (W_QU + EMBED*RANK)
#define W_KU (W_KD + RANK*EMBED)
#define W_VD (W_KU + EMBED*RANK)
#define W_VU (W_VD + RANK*EMBED)
#define W_O  (W_VU + EMBED*RANK)
#define W_TOT (W_O + EMBED*EMBED)
__device__ __nv_bfloat16 g_wHi[W_TOT];
__device__ __nv_bfloat16 g_wLo[W_TOT];

__device__ float g_Q[MTOK * EMBED];
__device__ float g_K[MTOK * EMBED];
__device__ float g_V[MTOK * EMBED];
__device__ float g_kvks[Bv * HEADS * (HDIM * HDIM + HDIM)];
#define KV_ELEMS (Bv * HEADS * HDIM * HDIM)
#define KS_ELEMS (Bv * HEADS * HDIM)

// ---------------------------------------------------------------------------
// helpers
// ---------------------------------------------------------------------------
__device__ __forceinline__ uint32_t smem_u32(const void* p) {
    uint32_t a;
    asm("{ .reg .u64 t; cvta.to.shared.u64 t, %1; cvt.u32.u64 %0, t; }"
        : "=r"(a) : "l"(p));
    return a;
}

__device__ __forceinline__ void ldsm4(uint32_t* r, uint32_t addr) {
    asm volatile("ldmatrix.sync.aligned.m8n8.x4.shared.b16 {%0,%1,%2,%3}, [%4];"
        : "=r"(r[0]), "=r"(r[1]), "=r"(r[2]), "=r"(r[3]) : "r"(addr));
}

__device__ __forceinline__ void mma16816(float* c, const uint32_t* a, const uint32_t* b) {
    asm volatile("mma.sync.aligned.m16n8k16.row.col.f32.bf16.bf16.f32 "
        "{%0,%1,%2,%3}, {%4,%5,%6,%7}, {%8,%9}, {%0,%1,%2,%3};"
        : "+f"(c[0]), "+f"(c[1]), "+f"(c[2]), "+f"(c[3])
        : "r"(a[0]), "r"(a[1]), "r"(a[2]), "r"(a[3]), "r"(b[0]), "r"(b[1]));
}

#define CP_ASYNC16(so, ga) \
    asm volatile("cp.async.cg.shared.global [%0], [%1], 16;\n" :: "r"(so), "l"(ga))
#define CP_COMMIT() asm volatile("cp.async.commit_group;\n" ::: "memory")
#define CP_WAIT(n)  asm volatile("cp.async.wait_group %0;\n" :: "n"(n) : "memory")

// ---------------------------------------------------------------------------
// split kernel: x fp32 -> (hi, lo) bf16
// ---------------------------------------------------------------------------
__global__ void split_kernel(const float* __restrict__ x,
                             __nv_bfloat16* __restrict__ hi,
                             __nv_bfloat16* __restrict__ lo, int n4)
{
    int i = blockIdx.x * blockDim.x + threadIdx.x;
    if (i >= n4) return;
    float4 v = reinterpret_cast<const float4*>(x)[i];
    __nv_bfloat16 h0 = __float2bfloat16(v.x), h1 = __float2bfloat16(v.y);
    __nv_bfloat16 h2 = __float2bfloat16(v.z), h3 = __float2bfloat16(v.w);
    __nv_bfloat16 l0 = __float2bfloat16(v.x - __bfloat162float(h0));
    __nv_bfloat16 l1 = __float2bfloat16(v.y - __bfloat162float(h1));
    __nv_bfloat16 l2 = __float2bfloat16(v.z - __bfloat162float(h2));
    __nv_bfloat16 l3 = __float2bfloat16(v.w - __bfloat162float(h3));
    __nv_bfloat162* hp = reinterpret_cast<__nv_bfloat162*>(hi);
    __nv_bfloat162* lp = reinterpret_cast<__nv_bfloat162*>(lo);
    hp[2*i]   = __halves2bfloat162(h0, h1);
    hp[2*i+1] = __halves2bfloat162(h2, h3);
    lp[2*i]   = __halves2bfloat162(l0, l1);
    lp[2*i+1] = __halves2bfloat162(l2, l3);
}

// ---------------------------------------------------------------------------
// mma.sync split-bf16 NT GEMM: C[m,n] = sum_k A[m,k]*B[n,k]
// 3 passes: Ahi*Bhi + Ahi*Blo + Alo*Bhi, fp32 accum in registers.
// Tile 128x128, BK=32, 8 warps (warp tile 64x32), 3-stage cp.async.
// SMEM rows strided 80B (conflict-free ldmatrix).
// MODE 0: bf16 split out. MODE 1: fp32 bias+elu+1. MODE 2: fp32 + bias.
// ---------------------------------------------------------------------------
#define BKC        32
#define RSTRIDE_B  80                       // bytes per smem row
#define TILE_BY    (128 * RSTRIDE_B)        // 10240 bytes per tile
#define STAGE_BY   (4 * TILE_BY)            // Ahi Alo Bhi Blo = 40960
#define NSTAGE     3
#define SMEM_GEMM  (NSTAGE * STAGE_BY)      // 122880

__device__ __forceinline__ void load_stage_mma(
    uint32_t sb, int tid, int s, int k0,
    const __nv_bfloat16* __restrict__ Ahi, const __nv_bfloat16* __restrict__ Alo,
    const __nv_bfloat16* __restrict__ Bhi, const __nv_bfloat16* __restrict__ Blo,
    int K, int aRow0, int bRow0)
{
    const uint32_t stage = sb + (uint32_t)s * STAGE_BY;
#pragma unroll
    for (int i = 0; i < 8; ++i) {
        int idx = tid + i * 256;            // 0..2047
        int tile = idx >> 9;                // /512 -> 0..3
        int w = idx & 511;
        int row = w >> 2;                   // 0..127
        int cb = w & 3;                     // 16B chunk (64B of data per row)
        const __nv_bfloat16* gp;
        int r0;
        if (tile == 0)      { gp = Ahi; r0 = aRow0; }
        else if (tile == 1) { gp = Alo; r0 = aRow0; }
        else if (tile == 2) { gp = Bhi; r0 = bRow0; }
        else                { gp = Blo; r0 = bRow0; }
        const void* ga = gp + (size_t)(r0 + row) * K + k0 + cb * 8;
        uint32_t so = stage + (uint32_t)tile * TILE_BY + (uint32_t)row * RSTRIDE_B + cb * 16;
        CP_ASYNC16(so, ga);
    }
    CP_COMMIT();
}

template <int MODE>
__global__ __launch_bounds__(256, 1) void gemm_mma3(
    const __nv_bfloat16* __restrict__ Ahi, const __nv_bfloat16* __restrict__ Alo,
    const __nv_bfloat16* __restrict__ Bhi, const __nv_bfloat16* __restrict__ Blo,
    const float* __restrict__ bias, float* __restrict__ Cf,
    __nv_bfloat16* __restrict__ Chi, __nv_bfloat16* __restrict__ Clo,
    int Nn, int K)
{
    extern __shared__ char smem[];
    const uint32_t sb = smem_u32(smem);
    const int tid = threadIdx.x;
    const int wid = tid >> 5;
    const int lane = tid & 31;
    const int bn = blockIdx.x, bm = blockIdx.y;
    const int warp_m = wid >> 2;            // 0..1
    const int warp_n = wid & 3;             // 0..3
    const int aRow0 = bm * 128, bRow0 = bn * 128;

    float acc[4][4][4];
#pragma unroll
    for (int mt = 0; mt < 4; ++mt)
#pragma unroll
        for (int nt = 0; nt < 4; ++nt)
#pragma unroll
            for (int j = 0; j < 4; ++j) acc[mt][nt][j] = 0.f;

    const int nch = K / BKC;                // 16 or 32

    load_stage_mma(sb, tid, 0, 0,     Ahi, Alo, Bhi, Blo, K, aRow0, bRow0);
    load_stage_mma(sb, tid, 1, BKC,   Ahi, Alo, Bhi, Blo, K, aRow0, bRow0);

    // lane-dependent ldmatrix address components
    const int a_r = lane & 15;              // row within 16-row tile
    const int a_c = (lane >> 4) * 8;        // col 0 or 8 within 16-k slice
    const int b_n = ((lane >> 4) << 3) + (lane & 7);   // n within 16-n pair
    const int b_k = ((lane >> 3) & 1) * 8;  // k 0 or 8 within 16-k slice

    for (int c = 0; c < nch; ++c) {
        if (c == nch - 1) { CP_WAIT(0); } else { CP_WAIT(1); }
        __syncthreads();

        if (c + 2 < nch)
            load_stage_mma(sb, tid, (c + 2) % NSTAGE, (c + 2) * BKC,
                           Ahi, Alo, Bhi, Blo, K, aRow0, bRow0);

        const uint32_t st = sb + (uint32_t)(c % NSTAGE) * STAGE_BY;
#pragma unroll
        for (int ks = 0; ks < 2; ++ks) {
            const int k0 = ks * 16;
            uint32_t ahi[4][4], alo[4][4];
#pragma unroll
            for (int mt = 0; mt < 4; ++mt) {
                uint32_t off = (uint32_t)(warp_m * 64 + mt * 16 + a_r) * RSTRIDE_B
                             + (uint32_t)(k0 + a_c) * 2;
                ldsm4(ahi[mt], st + 0 * TILE_BY + off);
                ldsm4(alo[mt], st + 1 * TILE_BY + off);
            }
            uint32_t bhi[4][2], blo[4][2];
#pragma unroll
            for (int nt2 = 0; nt2 < 2; ++nt2) {
                uint32_t off = (uint32_t)(warp_n * 32 + nt2 * 16 + b_n) * RSTRIDE_B
                             + (uint32_t)(k0 + b_k) * 2;
                uint32_t t4[4];
                ldsm4(t4, st + 2 * TILE_BY + off);
                bhi[nt2*2][0] = t4[0]; bhi[nt2*2][1] = t4[1];
                bhi[nt2*2+1][0] = t4[2]; bhi[nt2*2+1][1] = t4[3];
                ldsm4(t4, st + 3 * TILE_BY + off);
                blo[nt2*2][0] = t4[0]; blo[nt2*2][1] = t4[1];
                blo[nt2*2+1][0] = t4[2]; blo[nt2*2+1][1] = t4[3];
            }
#pragma unroll
            for (int mt = 0; mt < 4; ++mt)
#pragma unroll
                for (int nt = 0; nt < 4; ++nt) {
                    mma16816(acc[mt][nt], ahi[mt], bhi[nt]);
                    mma16816(acc[mt][nt], ahi[mt], blo[nt]);
                    mma16816(acc[mt][nt], alo[mt], bhi[nt]);
                }
        }
    }

    // epilogue
#pragma unroll
    for (int mt = 0; mt < 4; ++mt) {
#pragma unroll
        for (int nt = 0; nt < 4; ++nt) {
            const int row0 = bm * 128 + warp_m * 64 + mt * 16 + (lane >> 2);
            const int col  = bn * 128 + warp_n * 32 + nt * 8 + (lane & 3) * 2;
#pragma unroll
            for (int h = 0; h < 2; ++h) {
                const int row = row0 + h * 8;
                float f0 = acc[mt][nt][h * 2 + 0];
                float f1 = acc[mt][nt][h * 2 + 1];
                if (MODE == 0) {
                    __nv_bfloat16 h0 = __float2bfloat16(f0), h1 = __float2bfloat16(f1);
                    __nv_bfloat16 l0 = __float2bfloat16(f0 - __bfloat162float(h0));
                    __nv_bfloat16 l1 = __float2bfloat16(f1 - __bfloat162float(h1));
                    *reinterpret_cast<__nv_bfloat162*>(Chi + (size_t)row * Nn + col) =
                        __halves2bfloat162(h0, h1);
                    *reinterpret_cast<__nv_bfloat162*>(Clo + (size_t)row * Nn + col) =
                        __halves2bfloat162(l0, l1);
                } else {
                    f0 += __ldg(bias + col);
                    f1 += __ldg(bias + col + 1);
                    if (MODE == 1) {
                        f0 = (f0 > 0.f) ? (f0 + 1.f) : __expf(f0);
                        f1 = (f1 > 0.f) ? (f1 + 1.f) : __expf(f1);
                    }
                    *reinterpret_cast<float2*>(Cf + (size_t)row * Nn + col) =
                        make_float2(f0, f1);
                }
            }
        }
    }
}

// ---------------------------------------------------------------------------
// zero kernel
// ---------------------------------------------------------------------------
__global__ void zero_kernel(float* __restrict__ p, int n)
{
    int i = blockIdx.x * blockDim.x + threadIdx.x;
    if (i < n) p[i] = 0.f;
}

// ---------------------------------------------------------------------------
// kv[bh][d][e] = sum_n k[bh][n][d] * v[bh][n][e];  ksum[bh][d] = sum_n k
// ---------------------------------------------------------------------------
#define KV_CH 512

__global__ __launch_bounds__(256) void kv_ksum_kernel(
    const float* __restrict__ Km, const float* __restrict__ Vm,
    float* __restrict__ kv, float* __restrict__ ksum)
{
    const int bh = blockIdx.x;
    const int b = bh >> 4, h = bh & 15;
    const int chunk = blockIdx.y;
    const int tid = threadIdx.x;

    __shared__ float sk[8][64];
    __shared__ float sv[8][64];

    const int d  = tid >> 2;
    const int e0 = (tid & 3) * 16;

    float acc[16];
#pragma unroll
    for (int j = 0; j < 16; ++j) acc[j] = 0.f;
    float ks = 0.f;

    const size_t base = ((size_t)b * Nseq + (size_t)chunk * KV_CH) * EMBED + h * HDIM;
    const int r0 = tid >> 6, c0 = tid & 63;
    const int r1 = (tid + 256) >> 6, c1 = tid & 63;

    for (int p = 0; p < KV_CH / 8; ++p) {
        const size_t rb = base + (size_t)p * 8 * EMBED;
        sk[r0][c0] = Km[rb + (size_t)r0 * EMBED + c0];
        sk[r1][c1] = Km[rb + (size_t)r1 * EMBED + c1];
        sv[r0][c0] = Vm[rb + (size_t)r0 * EMBED + c0];
        sv[r1][c1] = Vm[rb + (size_t)r1 * EMBED + c1];
        __syncthreads();
#pragma unroll
        for (int r = 0; r < 8; ++r) {
            const float kd = sk[r][d];
            ks += kd;
#pragma unroll
            for (int j = 0; j < 16; ++j)
                acc[j] = fmaf(kd, sv[r][e0 + j], acc[j]);
        }
        __syncthreads();
    }

    float* kvp = kv + (size_t)bh * (HDIM * HDIM) + d * HDIM + e0;
#pragma unroll
    for (int j = 0; j < 16; ++j) atomicAdd(kvp + j, acc[j]);
    if ((tid & 3) == 0) atomicAdd(ksum + bh * HDIM + d, ks);
}

// ---------------------------------------------------------------------------
// attn: out = (q @ kv) / (q . ksum + 1e-6); writes bf16 split for Wo GEMM
// ---------------------------------------------------------------------------
__global__ __launch_bounds__(256) void attn_kernel(
    const float* __restrict__ Qm, const float* __restrict__ kv,
    const float* __restrict__ ksum,
    __nv_bfloat16* __restrict__ outHi, __nv_bfloat16* __restrict__ outLo)
{
    const int bh = blockIdx.x;
    const int b = bh >> 4, h = bh & 15;
    const int nt = blockIdx.y;
    const int tid = threadIdx.x;

    __shared__ float kv_s[64][65];
    __shared__ float ks_s[64];
    __shared__ float q_s[128][65];

    for (int i = tid; i < 4096; i += 256)
        kv_s[i >> 6][i & 63] = kv[(size_t)bh * 4096 + i];
    if (tid < 64) ks_s[tid] = ksum[bh * 64 + tid];

    const size_t base = ((size_t)b * Nseq + (size_t)nt * 128) * EMBED + h * HDIM;
    for (int i = tid; i < 128 * 64; i += 256) {
        const int r = i >> 6, c = i & 63;
        q_s[r][c] = Qm[base + (size_t)r * EMBED + c];
    }
    __syncthreads();

    const int t  = tid >> 1;
    const int e0 = (tid & 1) * 32;

    float denom = 0.f;
#pragma unroll
    for (int d2 = 0; d2 < 64; ++d2)
        denom = fmaf(q_s[t][d2], ks_s[d2], denom);
    denom += 1e-6f;

    float acc[32];
#pragma unroll
    for (int j = 0; j < 32; ++j) acc[j] = 0.f;
#pragma unroll 4
    for (int d2 = 0; d2 < 64; ++d2) {
        const float qd = q_s[t][d2];
#pragma unroll
        for (int j = 0; j < 32; ++j)
            acc[j] = fmaf(qd, kv_s[d2][e0 + j], acc[j]);
    }

    const float inv = 1.0f / denom;
    const size_t ob = base + (size_t)t * EMBED + e0;
    __nv_bfloat162* hp = reinterpret_cast<__nv_bfloat162*>(outHi + ob);
    __nv_bfloat162* lp = reinterpret_cast<__nv_bfloat162*>(outLo + ob);
#pragma unroll
    for (int j = 0; j < 32; j += 2) {
        float f0 = acc[j] * inv, f1 = acc[j + 1] * inv;
        __nv_bfloat16 h0 = __float2bfloat16(f0), h1 = __float2bfloat16(f1);
        __nv_bfloat16 l0 = __float2bfloat16(f0 - __bfloat162float(h0));
        __nv_bfloat16 l1 = __float2bfloat16(f1 - __bfloat162float(h1));
        hp[j >> 1] = __halves2bfloat162(h0, h1);
        lp[j >> 1] = __halves2bfloat162(l0, l1);
    }
}

// ---------------------------------------------------------------------------
// launch
// ---------------------------------------------------------------------------
extern "C" void kernel_launch(void* const* d_in, const int* in_sizes, int n_in,
                              void* d_out, int out_size)
{
    const float* query   = (const float*)d_in[0];
    const float* key_    = (const float*)d_in[1];
    const float* value   = (const float*)d_in[2];
    const float* Wq_down = (const float*)d_in[3];
    const float* Wq_up   = (const float*)d_in[4];
    const float* bq_up   = (const float*)d_in[5];
    const float* Wk_down = (const float*)d_in[6];
    const float* Wk_up   = (const float*)d_in[7];
    const float* bk_up   = (const float*)d_in[8];
    const float* Wv_down = (const float*)d_in[9];
    const float* Wv_up   = (const float*)d_in[10];
    const float* bv_up   = (const float*)d_in[11];
    const float* Wo      = (const float*)d_in[12];
    const float* bo      = (const float*)d_in[13];
    float* out = (float*)d_out;

    __nv_bfloat16 *inHi, *inLo, *yHi, *yLo, *atHi, *atLo, *wHi, *wLo;
    float *Q, *K, *V, *KVKS;
    cudaGetSymbolAddress((void**)&inHi, g_inHi);
    cudaGetSymbolAddress((void**)&inLo, g_inLo);
    cudaGetSymbolAddress((void**)&yHi,  g_yHi);
    cudaGetSymbolAddress((void**)&yLo,  g_yLo);
    cudaGetSymbolAddress((void**)&atHi, g_atHi);
    cudaGetSymbolAddress((void**)&atLo, g_atLo);
    cudaGetSymbolAddress((void**)&wHi,  g_wHi);
    cudaGetSymbolAddress((void**)&wLo,  g_wLo);
    cudaGetSymbolAddress((void**)&Q,    g_Q);
    cudaGetSymbolAddress((void**)&K,    g_K);
    cudaGetSymbolAddress((void**)&V,    g_V);
    cudaGetSymbolAddress((void**)&KVKS, g_kvks);
    float* KV = KVKS;
    float* KS = KVKS + KV_ELEMS;

    cudaFuncSetAttribute((const void*)gemm_mma3<0>, cudaFuncAttributeMaxDynamicSharedMemorySize, SMEM_GEMM);
    cudaFuncSetAttribute((const void*)gemm_mma3<1>, cudaFuncAttributeMaxDynamicSharedMemorySize, SMEM_GEMM);
    cudaFuncSetAttribute((const void*)gemm_mma3<2>, cudaFuncAttributeMaxDynamicSharedMemorySize, SMEM_GEMM);

    const dim3 blk(256);
    const dim3 gdown(RANK / 128, MTOK / 128);    // (4, 256)
    const dim3 gup(EMBED / 128, MTOK / 128);     // (8, 256)

    // weight splits
    split_kernel<<<(RANK*EMBED/4 + 255)/256, 256>>>(Wq_down, wHi + W_QD, wLo + W_QD, RANK*EMBED/4);
    split_kernel<<<(EMBED*RANK/4 + 255)/256, 256>>>(Wq_up,   wHi + W_QU, wLo + W_QU, EMBED*RANK/4);
    split_kernel<<<(RANK*EMBED/4 + 255)/256, 256>>>(Wk_down, wHi + W_KD, wLo + W_KD, RANK*EMBED/4);
    split_kernel<<<(EMBED*RANK/4 + 255)/256, 256>>>(Wk_up,   wHi + W_KU, wLo + W_KU, EMBED*RANK/4);
    split_kernel<<<(RANK*EMBED/4 + 255)/256, 256>>>(Wv_down, wHi + W_VD, wLo + W_VD, RANK*EMBED/4);
    split_kernel<<<(EMBED*RANK/4 + 255)/256, 256>>>(Wv_up,   wHi + W_VU, wLo + W_VU, EMBED*RANK/4);
    split_kernel<<<(EMBED*EMBED/4 + 255)/256, 256>>>(Wo,     wHi + W_O,  wLo + W_O,  EMBED*EMBED/4);

    const int nAct4 = MTOK * EMBED / 4;

    // Q path
    split_kernel<<<(nAct4 + 255)/256, 256>>>(query, inHi, inLo, nAct4);
    gemm_mma3<0><<<gdown, blk, SMEM_GEMM>>>(inHi, inLo, wHi + W_QD, wLo + W_QD,
                                            nullptr, nullptr, yHi, yLo, RANK, EMBED);
    gemm_mma3<1><<<gup, blk, SMEM_GEMM>>>(yHi, yLo, wHi + W_QU, wLo + W_QU,
                                          bq_up, Q, nullptr, nullptr, EMBED, RANK);
    // K path
    split_kernel<<<(nAct4 + 255)/256, 256>>>(key_, inHi, inLo, nAct4);
    gemm_mma3<0><<<gdown, blk, SMEM_GEMM>>>(inHi, inLo, wHi + W_KD, wLo + W_KD,
                                            nullptr, nullptr, yHi, yLo, RANK, EMBED);
    gemm_mma3<1><<<gup, blk, SMEM_GEMM>>>(yHi, yLo, wHi + W_KU, wLo + W_KU,
                                          bk_up, K, nullptr, nullptr, EMBED, RANK);
    // V path
    split_kernel<<<(nAct4 + 255)/256, 256>>>(value, inHi, inLo, nAct4);
    gemm_mma3<0><<<gdown, blk, SMEM_GEMM>>>(inHi, inLo, wHi + W_VD, wLo + W_VD,
                                            nullptr, nullptr, yHi, yLo, RANK, EMBED);
    gemm_mma3<2><<<gup, blk, SMEM_GEMM>>>(yHi, yLo, wHi + W_VU, wLo + W_VU,
                                          bv_up, V, nullptr, nullptr, EMBED, RANK);

    // kv / ksum reduction
    const int nz = KV_ELEMS + KS_ELEMS;
    zero_kernel<<<(nz + 255) / 256, 256>>>(KVKS, nz);
    kv_ksum_kernel<<<dim3(Bv * HEADS, Nseq / KV_CH), blk>>>(K, V, KV, KS);

    // attention (writes bf16 split)
    attn_kernel<<<dim3(Bv * HEADS, Nseq / 128), blk>>>(Q, KV, KS, atHi, atLo);

    // output projection
    gemm_mma3<2><<<gup, blk, SMEM_GEMM>>>(atHi, atLo, wHi + W_O, wLo + W_O,
                                          bo, out, nullptr, nullptr, EMBED, EMBED);
}

// round 6
// speedup vs baseline: 2.0539x; 1.0382x over previous
#include <cuda_runtime.h>
#include <cuda_bf16.h>
#include <cstdint>

// ---------------------------------------------------------------------------
// Problem constants
// ---------------------------------------------------------------------------
#define Bv     4
#define Nseq   8192
#define EMBED  1024
#define HEADS  16
#define HDIM   64
#define RANK   512
#define MTOK   (Bv * Nseq)          // 32768

// ---------------------------------------------------------------------------
// Scratch (__device__ globals; allocation forbidden)
// ---------------------------------------------------------------------------
__device__ __nv_bfloat16 g_inHi[MTOK * EMBED];
__device__ __nv_bfloat16 g_inLo[MTOK * EMBED];
__device__ __nv_bfloat16 g_yHi [MTOK * RANK];
__device__ __nv_bfloat16 g_yLo [MTOK * RANK];
__device__ __nv_bfloat16 g_atHi[MTOK * EMBED];
__device__ __nv_bfloat16 g_atLo[MTOK * EMBED];

#define W_QD 0
#define W_QU (W_QD + RANK*EMBED)
#define W_KD (W_QU + EMBED*RANK)
#define W_KU (W_KD + RANK*EMBED)
#define W_VD (W_KU + EMBED*RANK)
#define W_VU (W_VD + RANK*EMBED)
#define W_O  (W_VU + EMBED*RANK)
#define W_TOT (W_O + EMBED*EMBED)
__device__ __nv_bfloat16 g_wHi[W_TOT];
__device__ __nv_bfloat16 g_wLo[W_TOT];

__device__ float g_Q[MTOK * EMBED];
__device__ float g_K[MTOK * EMBED];
__device__ float g_V[MTOK * EMBED];
__device__ float g_kvks[Bv * HEADS * (HDIM * HDIM + HDIM)];
#define KV_ELEMS (Bv * HEADS * HDIM * HDIM)
#define KS_ELEMS (Bv * HEADS * HDIM)

// ---------------------------------------------------------------------------
// helpers
// ---------------------------------------------------------------------------
__device__ __forceinline__ uint32_t smem_u32(const void* p) {
    uint32_t a;
    asm("{ .reg .u64 t; cvta.to.shared.u64 t, %1; cvt.u32.u64 %0, t; }"
        : "=r"(a) : "l"(p));
    return a;
}

__device__ __forceinline__ void ldsm4(uint32_t* r, uint32_t addr) {
    asm volatile("ldmatrix.sync.aligned.m8n8.x4.shared.b16 {%0,%1,%2,%3}, [%4];"
        : "=r"(r[0]), "=r"(r[1]), "=r"(r[2]), "=r"(r[3]) : "r"(addr));
}

__device__ __forceinline__ void mma16816(float* c, const uint32_t* a, const uint32_t* b) {
    asm volatile("mma.sync.aligned.m16n8k16.row.col.f32.bf16.bf16.f32 "
        "{%0,%1,%2,%3}, {%4,%5,%6,%7}, {%8,%9}, {%0,%1,%2,%3};"
        : "+f"(c[0]), "+f"(c[1]), "+f"(c[2]), "+f"(c[3])
        : "r"(a[0]), "r"(a[1]), "r"(a[2]), "r"(a[3]), "r"(b[0]), "r"(b[1]));
}

#define CP_ASYNC16(so, ga) \
    asm volatile("cp.async.cg.shared.global [%0], [%1], 16;\n" :: "r"(so), "l"(ga))
#define CP_COMMIT() asm volatile("cp.async.commit_group;\n" ::: "memory")
#define CP_WAIT(n)  asm volatile("cp.async.wait_group %0;\n" :: "n"(n) : "memory")

// ---------------------------------------------------------------------------
// split kernel: x fp32 -> (hi, lo) bf16
// ---------------------------------------------------------------------------
__global__ void split_kernel(const float* __restrict__ x,
                             __nv_bfloat16* __restrict__ hi,
                             __nv_bfloat16* __restrict__ lo, int n4)
{
    int i = blockIdx.x * blockDim.x + threadIdx.x;
    if (i >= n4) return;
    float4 v = reinterpret_cast<const float4*>(x)[i];
    __nv_bfloat16 h0 = __float2bfloat16(v.x), h1 = __float2bfloat16(v.y);
    __nv_bfloat16 h2 = __float2bfloat16(v.z), h3 = __float2bfloat16(v.w);
    __nv_bfloat16 l0 = __float2bfloat16(v.x - __bfloat162float(h0));
    __nv_bfloat16 l1 = __float2bfloat16(v.y - __bfloat162float(h1));
    __nv_bfloat16 l2 = __float2bfloat16(v.z - __bfloat162float(h2));
    __nv_bfloat16 l3 = __float2bfloat16(v.w - __bfloat162float(h3));
    __nv_bfloat162* hp = reinterpret_cast<__nv_bfloat162*>(hi);
    __nv_bfloat162* lp = reinterpret_cast<__nv_bfloat162*>(lo);
    hp[2*i]   = __halves2bfloat162(h0, h1);
    hp[2*i+1] = __halves2bfloat162(h2, h3);
    lp[2*i]   = __halves2bfloat162(l0, l1);
    lp[2*i+1] = __halves2bfloat162(l2, l3);
}

// ---------------------------------------------------------------------------
// mma.sync split-bf16 NT GEMM: C[m,n] = sum_k A[m,k]*B[n,k]
// 3 passes: Ahi*Bhi + Ahi*Blo + Alo*Bhi, fp32 accum in registers.
// Tile 256x128, BK=32, 16 warps (4x4, warp tile 64x32), 3-stage cp.async.
// SMEM rows strided 80B (conflict-free ldmatrix).
// MODE 0: bf16 split out. MODE 1: fp32 bias+elu+1. MODE 2: fp32 + bias.
// ---------------------------------------------------------------------------
#define BKC        32
#define RSTRIDE_B  80
#define A_TILE_BY  (256 * RSTRIDE_B)        // 20480
#define B_TILE_BY  (128 * RSTRIDE_B)        // 10240
#define STAGE_BY   (2 * A_TILE_BY + 2 * B_TILE_BY)  // 61440
#define NSTAGE     3
#define SMEM_GEMM  (NSTAGE * STAGE_BY)      // 184320
#define OFF_AHI    0
#define OFF_ALO    A_TILE_BY
#define OFF_BHI    (2 * A_TILE_BY)
#define OFF_BLO    (2 * A_TILE_BY + B_TILE_BY)

__device__ __forceinline__ void load_stage_mma(
    uint32_t sb, int tid, int s, int k0,
    const __nv_bfloat16* __restrict__ Ahi, const __nv_bfloat16* __restrict__ Alo,
    const __nv_bfloat16* __restrict__ Bhi, const __nv_bfloat16* __restrict__ Blo,
    int K, int aRow0, int bRow0)
{
    const uint32_t stage = sb + (uint32_t)s * STAGE_BY;
#pragma unroll
    for (int i = 0; i < 6; ++i) {
        int idx = tid + i * 512;            // 0..3071
        const __nv_bfloat16* gp;
        int r0, row, cb;
        uint32_t tbase;
        if (idx < 2048) {                   // A tiles: 1024 chunks each
            int at = idx >> 10;             // 0 = hi, 1 = lo
            int w = idx & 1023;
            row = w >> 2; cb = w & 3;
            gp = at ? Alo : Ahi; r0 = aRow0;
            tbase = at ? OFF_ALO : OFF_AHI;
        } else {                            // B tiles: 512 chunks each
            int bidx = idx - 2048;
            int bt = bidx >> 9;             // 0 = hi, 1 = lo
            int w = bidx & 511;
            row = w >> 2; cb = w & 3;
            gp = bt ? Blo : Bhi; r0 = bRow0;
            tbase = bt ? OFF_BLO : OFF_BHI;
        }
        const void* ga = gp + (size_t)(r0 + row) * K + k0 + cb * 8;
        uint32_t so = stage + tbase + (uint32_t)row * RSTRIDE_B + cb * 16;
        CP_ASYNC16(so, ga);
    }
    CP_COMMIT();
}

template <int MODE>
__global__ __launch_bounds__(512, 1) void gemm_mma3(
    const __nv_bfloat16* __restrict__ Ahi, const __nv_bfloat16* __restrict__ Alo,
    const __nv_bfloat16* __restrict__ Bhi, const __nv_bfloat16* __restrict__ Blo,
    const float* __restrict__ bias, float* __restrict__ Cf,
    __nv_bfloat16* __restrict__ Chi, __nv_bfloat16* __restrict__ Clo,
    int Nn, int K)
{
    extern __shared__ char smem[];
    const uint32_t sb = smem_u32(smem);
    const int tid = threadIdx.x;
    const int wid = tid >> 5;
    const int lane = tid & 31;
    const int bn = blockIdx.x, bm = blockIdx.y;
    const int warp_m = wid >> 2;            // 0..3  (64 rows each)
    const int warp_n = wid & 3;             // 0..3  (32 cols each)
    const int aRow0 = bm * 256, bRow0 = bn * 128;

    float acc[4][4][4];
#pragma unroll
    for (int mt = 0; mt < 4; ++mt)
#pragma unroll
        for (int nt = 0; nt < 4; ++nt)
#pragma unroll
            for (int j = 0; j < 4; ++j) acc[mt][nt][j] = 0.f;

    const int nch = K / BKC;                // 16 or 32

    load_stage_mma(sb, tid, 0, 0,     Ahi, Alo, Bhi, Blo, K, aRow0, bRow0);
    load_stage_mma(sb, tid, 1, BKC,   Ahi, Alo, Bhi, Blo, K, aRow0, bRow0);

    const int a_r = lane & 15;
    const int a_c = (lane >> 4) * 8;
    const int b_n = ((lane >> 4) << 3) + (lane & 7);
    const int b_k = ((lane >> 3) & 1) * 8;

    for (int c = 0; c < nch; ++c) {
        if (c == nch - 1) { CP_WAIT(0); } else { CP_WAIT(1); }
        __syncthreads();

        if (c + 2 < nch)
            load_stage_mma(sb, tid, (c + 2) % NSTAGE, (c + 2) * BKC,
                           Ahi, Alo, Bhi, Blo, K, aRow0, bRow0);

        const uint32_t st = sb + (uint32_t)(c % NSTAGE) * STAGE_BY;
#pragma unroll
        for (int ks = 0; ks < 2; ++ks) {
            const int k0 = ks * 16;
            uint32_t ahi[4][4], alo[4][4];
#pragma unroll
            for (int mt = 0; mt < 4; ++mt) {
                uint32_t off = (uint32_t)(warp_m * 64 + mt * 16 + a_r) * RSTRIDE_B
                             + (uint32_t)(k0 + a_c) * 2;
                ldsm4(ahi[mt], st + OFF_AHI + off);
                ldsm4(alo[mt], st + OFF_ALO + off);
            }
            uint32_t bhi[4][2], blo[4][2];
#pragma unroll
            for (int nt2 = 0; nt2 < 2; ++nt2) {
                uint32_t off = (uint32_t)(warp_n * 32 + nt2 * 16 + b_n) * RSTRIDE_B
                             + (uint32_t)(k0 + b_k) * 2;
                uint32_t t4[4];
                ldsm4(t4, st + OFF_BHI + off);
                bhi[nt2*2][0] = t4[0]; bhi[nt2*2][1] = t4[1];
                bhi[nt2*2+1][0] = t4[2]; bhi[nt2*2+1][1] = t4[3];
                ldsm4(t4, st + OFF_BLO + off);
                blo[nt2*2][0] = t4[0]; blo[nt2*2][1] = t4[1];
                blo[nt2*2+1][0] = t4[2]; blo[nt2*2+1][1] = t4[3];
            }
#pragma unroll
            for (int mt = 0; mt < 4; ++mt)
#pragma unroll
                for (int nt = 0; nt < 4; ++nt) {
                    mma16816(acc[mt][nt], ahi[mt], bhi[nt]);
                    mma16816(acc[mt][nt], ahi[mt], blo[nt]);
                    mma16816(acc[mt][nt], alo[mt], bhi[nt]);
                }
        }
    }

    // epilogue
#pragma unroll
    for (int mt = 0; mt < 4; ++mt) {
#pragma unroll
        for (int nt = 0; nt < 4; ++nt) {
            const int row0 = bm * 256 + warp_m * 64 + mt * 16 + (lane >> 2);
            const int col  = bn * 128 + warp_n * 32 + nt * 8 + (lane & 3) * 2;
#pragma unroll
            for (int h = 0; h < 2; ++h) {
                const int row = row0 + h * 8;
                float f0 = acc[mt][nt][h * 2 + 0];
                float f1 = acc[mt][nt][h * 2 + 1];
                if (MODE == 0) {
                    __nv_bfloat16 h0 = __float2bfloat16(f0), h1 = __float2bfloat16(f1);
                    __nv_bfloat16 l0 = __float2bfloat16(f0 - __bfloat162float(h0));
                    __nv_bfloat16 l1 = __float2bfloat16(f1 - __bfloat162float(h1));
                    *reinterpret_cast<__nv_bfloat162*>(Chi + (size_t)row * Nn + col) =
                        __halves2bfloat162(h0, h1);
                    *reinterpret_cast<__nv_bfloat162*>(Clo + (size_t)row * Nn + col) =
                        __halves2bfloat162(l0, l1);
                } else {
                    f0 += __ldg(bias + col);
                    f1 += __ldg(bias + col + 1);
                    if (MODE == 1) {
                        f0 = (f0 > 0.f) ? (f0 + 1.f) : __expf(f0);
                        f1 = (f1 > 0.f) ? (f1 + 1.f) : __expf(f1);
                    }
                    *reinterpret_cast<float2*>(Cf + (size_t)row * Nn + col) =
                        make_float2(f0, f1);
                }
            }
        }
    }
}

// ---------------------------------------------------------------------------
// zero kernel
// ---------------------------------------------------------------------------
__global__ void zero_kernel(float* __restrict__ p, int n)
{
    int i = blockIdx.x * blockDim.x + threadIdx.x;
    if (i < n) p[i] = 0.f;
}

// ---------------------------------------------------------------------------
// kv[bh][d][e] = sum_n k[bh][n][d] * v[bh][n][e];  ksum[bh][d] = sum_n k
// ---------------------------------------------------------------------------
#define KV_CH 512

__global__ __launch_bounds__(256) void kv_ksum_kernel(
    const float* __restrict__ Km, const float* __restrict__ Vm,
    float* __restrict__ kv, float* __restrict__ ksum)
{
    const int bh = blockIdx.x;
    const int b = bh >> 4, h = bh & 15;
    const int chunk = blockIdx.y;
    const int tid = threadIdx.x;

    __shared__ float sk[8][64];
    __shared__ float sv[8][64];

    const int d  = tid >> 2;
    const int e0 = (tid & 3) * 16;

    float acc[16];
#pragma unroll
    for (int j = 0; j < 16; ++j) acc[j] = 0.f;
    float ks = 0.f;

    const size_t base = ((size_t)b * Nseq + (size_t)chunk * KV_CH) * EMBED + h * HDIM;
    const int r0 = tid >> 6, c0 = tid & 63;
    const int r1 = (tid + 256) >> 6, c1 = tid & 63;

    for (int p = 0; p < KV_CH / 8; ++p) {
        const size_t rb = base + (size_t)p * 8 * EMBED;
        sk[r0][c0] = Km[rb + (size_t)r0 * EMBED + c0];
        sk[r1][c1] = Km[rb + (size_t)r1 * EMBED + c1];
        sv[r0][c0] = Vm[rb + (size_t)r0 * EMBED + c0];
        sv[r1][c1] = Vm[rb + (size_t)r1 * EMBED + c1];
        __syncthreads();
#pragma unroll
        for (int r = 0; r < 8; ++r) {
            const float kd = sk[r][d];
            ks += kd;
#pragma unroll
            for (int j = 0; j < 16; ++j)
                acc[j] = fmaf(kd, sv[r][e0 + j], acc[j]);
        }
        __syncthreads();
    }

    float* kvp = kv + (size_t)bh * (HDIM * HDIM) + d * HDIM + e0;
#pragma unroll
    for (int j = 0; j < 16; ++j) atomicAdd(kvp + j, acc[j]);
    if ((tid & 3) == 0) atomicAdd(ksum + bh * HDIM + d, ks);
}

// ---------------------------------------------------------------------------
// attn: out = (q @ kv) / (q . ksum + 1e-6); writes bf16 split for Wo GEMM
// ---------------------------------------------------------------------------
__global__ __launch_bounds__(256) void attn_kernel(
    const float* __restrict__ Qm, const float* __restrict__ kv,
    const float* __restrict__ ksum,
    __nv_bfloat16* __restrict__ outHi, __nv_bfloat16* __restrict__ outLo)
{
    const int bh = blockIdx.x;
    const int b = bh >> 4, h = bh & 15;
    const int nt = blockIdx.y;
    const int tid = threadIdx.x;

    __shared__ float kv_s[64][65];
    __shared__ float ks_s[64];
    __shared__ float q_s[128][65];

    for (int i = tid; i < 4096; i += 256)
        kv_s[i >> 6][i & 63] = kv[(size_t)bh * 4096 + i];
    if (tid < 64) ks_s[tid] = ksum[bh * 64 + tid];

    const size_t base = ((size_t)b * Nseq + (size_t)nt * 128) * EMBED + h * HDIM;
    for (int i = tid; i < 128 * 64; i += 256) {
        const int r = i >> 6, c = i & 63;
        q_s[r][c] = Qm[base + (size_t)r * EMBED + c];
    }
    __syncthreads();

    const int t  = tid >> 1;
    const int e0 = (tid & 1) * 32;

    float denom = 0.f;
#pragma unroll
    for (int d2 = 0; d2 < 64; ++d2)
        denom = fmaf(q_s[t][d2], ks_s[d2], denom);
    denom += 1e-6f;

    float acc[32];
#pragma unroll
    for (int j = 0; j < 32; ++j) acc[j] = 0.f;
#pragma unroll 4
    for (int d2 = 0; d2 < 64; ++d2) {
        const float qd = q_s[t][d2];
#pragma unroll
        for (int j = 0; j < 32; ++j)
            acc[j] = fmaf(qd, kv_s[d2][e0 + j], acc[j]);
    }

    const float inv = 1.0f / denom;
    const size_t ob = base + (size_t)t * EMBED + e0;
    __nv_bfloat162* hp = reinterpret_cast<__nv_bfloat162*>(outHi + ob);
    __nv_bfloat162* lp = reinterpret_cast<__nv_bfloat162*>(outLo + ob);
#pragma unroll
    for (int j = 0; j < 32; j += 2) {
        float f0 = acc[j] * inv, f1 = acc[j + 1] * inv;
        __nv_bfloat16 h0 = __float2bfloat16(f0), h1 = __float2bfloat16(f1);
        __nv_bfloat16 l0 = __float2bfloat16(f0 - __bfloat162float(h0));
        __nv_bfloat16 l1 = __float2bfloat16(f1 - __bfloat162float(h1));
        hp[j >> 1] = __halves2bfloat162(h0, h1);
        lp[j >> 1] = __halves2bfloat162(l0, l1);
    }
}

// ---------------------------------------------------------------------------
// launch
// ---------------------------------------------------------------------------
extern "C" void kernel_launch(void* const* d_in, const int* in_sizes, int n_in,
                              void* d_out, int out_size)
{
    const float* query   = (const float*)d_in[0];
    const float* key_    = (const float*)d_in[1];
    const float* value   = (const float*)d_in[2];
    const float* Wq_down = (const float*)d_in[3];
    const float* Wq_up   = (const float*)d_in[4];
    const float* bq_up   = (const float*)d_in[5];
    const float* Wk_down = (const float*)d_in[6];
    const float* Wk_up   = (const float*)d_in[7];
    const float* bk_up   = (const float*)d_in[8];
    const float* Wv_down = (const float*)d_in[9];
    const float* Wv_up   = (const float*)d_in[10];
    const float* bv_up   = (const float*)d_in[11];
    const float* Wo      = (const float*)d_in[12];
    const float* bo      = (const float*)d_in[13];
    float* out = (float*)d_out;

    __nv_bfloat16 *inHi, *inLo, *yHi, *yLo, *atHi, *atLo, *wHi, *wLo;
    float *Q, *K, *V, *KVKS;
    cudaGetSymbolAddress((void**)&inHi, g_inHi);
    cudaGetSymbolAddress((void**)&inLo, g_inLo);
    cudaGetSymbolAddress((void**)&yHi,  g_yHi);
    cudaGetSymbolAddress((void**)&yLo,  g_yLo);
    cudaGetSymbolAddress((void**)&atHi, g_atHi);
    cudaGetSymbolAddress((void**)&atLo, g_atLo);
    cudaGetSymbolAddress((void**)&wHi,  g_wHi);
    cudaGetSymbolAddress((void**)&wLo,  g_wLo);
    cudaGetSymbolAddress((void**)&Q,    g_Q);
    cudaGetSymbolAddress((void**)&K,    g_K);
    cudaGetSymbolAddress((void**)&V,    g_V);
    cudaGetSymbolAddress((void**)&KVKS, g_kvks);
    float* KV = KVKS;
    float* KS = KVKS + KV_ELEMS;

    cudaFuncSetAttribute((const void*)gemm_mma3<0>, cudaFuncAttributeMaxDynamicSharedMemorySize, SMEM_GEMM);
    cudaFuncSetAttribute((const void*)gemm_mma3<1>, cudaFuncAttributeMaxDynamicSharedMemorySize, SMEM_GEMM);
    cudaFuncSetAttribute((const void*)gemm_mma3<2>, cudaFuncAttributeMaxDynamicSharedMemorySize, SMEM_GEMM);

    const dim3 blk(512);
    const dim3 gdown(RANK / 128, MTOK / 256);    // (4, 128)
    const dim3 gup(EMBED / 128, MTOK / 256);     // (8, 128)

    // weight splits
    split_kernel<<<(RANK*EMBED/4 + 255)/256, 256>>>(Wq_down, wHi + W_QD, wLo + W_QD, RANK*EMBED/4);
    split_kernel<<<(EMBED*RANK/4 + 255)/256, 256>>>(Wq_up,   wHi + W_QU, wLo + W_QU, EMBED*RANK/4);
    split_kernel<<<(RANK*EMBED/4 + 255)/256, 256>>>(Wk_down, wHi + W_KD, wLo + W_KD, RANK*EMBED/4);
    split_kernel<<<(EMBED*RANK/4 + 255)/256, 256>>>(Wk_up,   wHi + W_KU, wLo + W_KU, EMBED*RANK/4);
    split_kernel<<<(RANK*EMBED/4 + 255)/256, 256>>>(Wv_down, wHi + W_VD, wLo + W_VD, RANK*EMBED/4);
    split_kernel<<<(EMBED*RANK/4 + 255)/256, 256>>>(Wv_up,   wHi + W_VU, wLo + W_VU, EMBED*RANK/4);
    split_kernel<<<(EMBED*EMBED/4 + 255)/256, 256>>>(Wo,     wHi + W_O,  wLo + W_O,  EMBED*EMBED/4);

    const int nAct4 = MTOK * EMBED / 4;

    // Q path
    split_kernel<<<(nAct4 + 255)/256, 256>>>(query, inHi, inLo, nAct4);
    gemm_mma3<0><<<gdown, blk, SMEM_GEMM>>>(inHi, inLo, wHi + W_QD, wLo + W_QD,
                                            nullptr, nullptr, yHi, yLo, RANK, EMBED);
    gemm_mma3<1><<<gup, blk, SMEM_GEMM>>>(yHi, yLo, wHi + W_QU, wLo + W_QU,
                                          bq_up, Q, nullptr, nullptr, EMBED, RANK);
    // K path
    split_kernel<<<(nAct4 + 255)/256, 256>>>(key_, inHi, inLo, nAct4);
    gemm_mma3<0><<<gdown, blk, SMEM_GEMM>>>(inHi, inLo, wHi + W_KD, wLo + W_KD,
                                            nullptr, nullptr, yHi, yLo, RANK, EMBED);
    gemm_mma3<1><<<gup, blk, SMEM_GEMM>>>(yHi, yLo, wHi + W_KU, wLo + W_KU,
                                          bk_up, K, nullptr, nullptr, EMBED, RANK);
    // V path
    split_kernel<<<(nAct4 + 255)/256, 256>>>(value, inHi, inLo, nAct4);
    gemm_mma3<0><<<gdown, blk, SMEM_GEMM>>>(inHi, inLo, wHi + W_VD, wLo + W_VD,
                                            nullptr, nullptr, yHi, yLo, RANK, EMBED);
    gemm_mma3<2><<<gup, blk, SMEM_GEMM>>>(yHi, yLo, wHi + W_VU, wLo + W_VU,
                                          bv_up, V, nullptr, nullptr, EMBED, RANK);

    // kv / ksum reduction
    const int nz = KV_ELEMS + KS_ELEMS;
    zero_kernel<<<(nz + 255) / 256, 256>>>(KVKS, nz);
    kv_ksum_kernel<<<dim3(Bv * HEADS, Nseq / KV_CH), dim3(256)>>>(K, V, KV, KS);

    // attention (writes bf16 split)
    attn_kernel<<<dim3(Bv * HEADS, Nseq / 128), dim3(256)>>>(Q, KV, KS, atHi, atLo);

    // output projection
    gemm_mma3<2><<<gup, blk, SMEM_GEMM>>>(atHi, atLo, wHi + W_O, wLo + W_O,
                                          bo, out, nullptr, nullptr, EMBED, EMBED);
}

// round 7
// speedup vs baseline: 3.4022x; 1.6565x over previous
#include <cuda_runtime.h>
#include <cuda_fp16.h>
#include <cstdint>

// ---------------------------------------------------------------------------
// Problem constants
// ---------------------------------------------------------------------------
#define Bv     4
#define Nseq   8192
#define EMBED  1024
#define HEADS  16
#define HDIM   64
#define RANK   512
#define MTOK   (Bv * Nseq)          // 32768

// ---------------------------------------------------------------------------
// Scratch (__device__ globals; allocation forbidden)
// ---------------------------------------------------------------------------
__device__ __half g_inH[MTOK * EMBED];   // fp16 of q/k/v input (reused)
__device__ __half g_yH [MTOK * RANK];    // low-rank intermediate
__device__ __half g_atH[MTOK * EMBED];   // attention output

#define W_QD 0
#define W_QU (W_QD + RANK*EMBED)
#define W_KD (W_QU + EMBED*RANK)
#define W_KU (W_KD + RANK*EMBED)
#define W_VD (W_KU + EMBED*RANK)
#define W_VU (W_VD + RANK*EMBED)
#define W_O  (W_VU + EMBED*RANK)
#define W_TOT (W_O + EMBED*EMBED)
__device__ __half g_wH[W_TOT];

__device__ float g_Q[MTOK * EMBED];
__device__ float g_K[MTOK * EMBED];
__device__ float g_V[MTOK * EMBED];
__device__ float g_kvks[Bv * HEADS * (HDIM * HDIM + HDIM)];
#define KV_ELEMS (Bv * HEADS * HDIM * HDIM)
#define KS_ELEMS (Bv * HEADS * HDIM)

// ---------------------------------------------------------------------------
// helpers
// ---------------------------------------------------------------------------
__device__ __forceinline__ uint32_t smem_u32(const void* p) {
    uint32_t a;
    asm("{ .reg .u64 t; cvta.to.shared.u64 t, %1; cvt.u32.u64 %0, t; }"
        : "=r"(a) : "l"(p));
    return a;
}

__device__ __forceinline__ void ldsm4(uint32_t* r, uint32_t addr) {
    asm volatile("ldmatrix.sync.aligned.m8n8.x4.shared.b16 {%0,%1,%2,%3}, [%4];"
        : "=r"(r[0]), "=r"(r[1]), "=r"(r[2]), "=r"(r[3]) : "r"(addr));
}

__device__ __forceinline__ void mma16816(float* c, const uint32_t* a, const uint32_t* b) {
    asm volatile("mma.sync.aligned.m16n8k16.row.col.f32.f16.f16.f32 "
        "{%0,%1,%2,%3}, {%4,%5,%6,%7}, {%8,%9}, {%0,%1,%2,%3};"
        : "+f"(c[0]), "+f"(c[1]), "+f"(c[2]), "+f"(c[3])
        : "r"(a[0]), "r"(a[1]), "r"(a[2]), "r"(a[3]), "r"(b[0]), "r"(b[1]));
}

#define CP_ASYNC16(so, ga) \
    asm volatile("cp.async.cg.shared.global [%0], [%1], 16;\n" :: "r"(so), "l"(ga))
#define CP_COMMIT() asm volatile("cp.async.commit_group;\n" ::: "memory")
#define CP_WAIT(n)  asm volatile("cp.async.wait_group %0;\n" :: "n"(n) : "memory")

// ---------------------------------------------------------------------------
// convert kernel: fp32 -> fp16
// ---------------------------------------------------------------------------
__global__ void cvt_kernel(const float* __restrict__ x,
                           __half* __restrict__ y, int n4)
{
    int i = blockIdx.x * blockDim.x + threadIdx.x;
    if (i >= n4) return;
    float4 v = reinterpret_cast<const float4*>(x)[i];
    __half2* yp = reinterpret_cast<__half2*>(y);
    yp[2*i]   = __floats2half2_rn(v.x, v.y);
    yp[2*i+1] = __floats2half2_rn(v.z, v.w);
}

// ---------------------------------------------------------------------------
// mma.sync fp16 NT GEMM: C[m,n] = sum_k A[m,k]*B[n,k], fp32 accum.
// Tile 256x128, BK=32, 16 warps (4x4, warp tile 64x32), 3-stage cp.async.
// SMEM rows strided 80B (conflict-free ldmatrix).
// MODE 0: fp16 out. MODE 1: fp32 bias+elu+1. MODE 2: fp32 + bias.
// ---------------------------------------------------------------------------
#define BKC        32
#define RSTRIDE_B  80
#define A_TILE_BY  (256 * RSTRIDE_B)        // 20480
#define B_TILE_BY  (128 * RSTRIDE_B)        // 10240
#define STAGE_BY   (A_TILE_BY + B_TILE_BY)  // 30720
#define NSTAGE     3
#define SMEM_GEMM  (NSTAGE * STAGE_BY)      // 92160
#define OFF_A      0
#define OFF_B      A_TILE_BY

__device__ __forceinline__ void load_stage_mma(
    uint32_t sb, int tid, int s, int k0,
    const __half* __restrict__ A, const __half* __restrict__ B,
    int K, int aRow0, int bRow0)
{
    const uint32_t stage = sb + (uint32_t)s * STAGE_BY;
#pragma unroll
    for (int i = 0; i < 3; ++i) {
        int idx = tid + i * 512;            // 0..1535
        const __half* gp;
        int r0, row, cb;
        uint32_t tbase;
        if (idx < 1024) {                   // A: 1024 chunks
            row = idx >> 2; cb = idx & 3;
            gp = A; r0 = aRow0; tbase = OFF_A;
        } else {                            // B: 512 chunks
            int w = idx - 1024;
            row = w >> 2; cb = w & 3;
            gp = B; r0 = bRow0; tbase = OFF_B;
        }
        const void* ga = gp + (size_t)(r0 + row) * K + k0 + cb * 8;
        uint32_t so = stage + tbase + (uint32_t)row * RSTRIDE_B + cb * 16;
        CP_ASYNC16(so, ga);
    }
    CP_COMMIT();
}

template <int MODE>
__global__ __launch_bounds__(512, 1) void gemm_mma1(
    const __half* __restrict__ A, const __half* __restrict__ B,
    const float* __restrict__ bias, float* __restrict__ Cf,
    __half* __restrict__ Ch,
    int Nn, int K)
{
    extern __shared__ char smem[];
    const uint32_t sb = smem_u32(smem);
    const int tid = threadIdx.x;
    const int wid = tid >> 5;
    const int lane = tid & 31;
    const int bn = blockIdx.x, bm = blockIdx.y;
    const int warp_m = wid >> 2;            // 0..3  (64 rows each)
    const int warp_n = wid & 3;             // 0..3  (32 cols each)
    const int aRow0 = bm * 256, bRow0 = bn * 128;

    float acc[4][4][4];
#pragma unroll
    for (int mt = 0; mt < 4; ++mt)
#pragma unroll
        for (int nt = 0; nt < 4; ++nt)
#pragma unroll
            for (int j = 0; j < 4; ++j) acc[mt][nt][j] = 0.f;

    const int nch = K / BKC;                // 16 or 32

    load_stage_mma(sb, tid, 0, 0,   A, B, K, aRow0, bRow0);
    load_stage_mma(sb, tid, 1, BKC, A, B, K, aRow0, bRow0);

    const int a_r = lane & 15;
    const int a_c = (lane >> 4) * 8;
    const int b_n = ((lane >> 4) << 3) + (lane & 7);
    const int b_k = ((lane >> 3) & 1) * 8;

    for (int c = 0; c < nch; ++c) {
        if (c == nch - 1) { CP_WAIT(0); } else { CP_WAIT(1); }
        __syncthreads();

        if (c + 2 < nch)
            load_stage_mma(sb, tid, (c + 2) % NSTAGE, (c + 2) * BKC,
                           A, B, K, aRow0, bRow0);

        const uint32_t st = sb + (uint32_t)(c % NSTAGE) * STAGE_BY;
#pragma unroll
        for (int ks = 0; ks < 2; ++ks) {
            const int k0 = ks * 16;
            uint32_t ar[4][4];
#pragma unroll
            for (int mt = 0; mt < 4; ++mt) {
                uint32_t off = (uint32_t)(warp_m * 64 + mt * 16 + a_r) * RSTRIDE_B
                             + (uint32_t)(k0 + a_c) * 2;
                ldsm4(ar[mt], st + OFF_A + off);
            }
            uint32_t br[4][2];
#pragma unroll
            for (int nt2 = 0; nt2 < 2; ++nt2) {
                uint32_t off = (uint32_t)(warp_n * 32 + nt2 * 16 + b_n) * RSTRIDE_B
                             + (uint32_t)(k0 + b_k) * 2;
                uint32_t t4[4];
                ldsm4(t4, st + OFF_B + off);
                br[nt2*2][0] = t4[0]; br[nt2*2][1] = t4[1];
                br[nt2*2+1][0] = t4[2]; br[nt2*2+1][1] = t4[3];
            }
#pragma unroll
            for (int mt = 0; mt < 4; ++mt)
#pragma unroll
                for (int nt = 0; nt < 4; ++nt)
                    mma16816(acc[mt][nt], ar[mt], br[nt]);
        }
    }

    // epilogue
#pragma unroll
    for (int mt = 0; mt < 4; ++mt) {
#pragma unroll
        for (int nt = 0; nt < 4; ++nt) {
            const int row0 = bm * 256 + warp_m * 64 + mt * 16 + (lane >> 2);
            const int col  = bn * 128 + warp_n * 32 + nt * 8 + (lane & 3) * 2;
#pragma unroll
            for (int h = 0; h < 2; ++h) {
                const int row = row0 + h * 8;
                float f0 = acc[mt][nt][h * 2 + 0];
                float f1 = acc[mt][nt][h * 2 + 1];
                if (MODE == 0) {
                    *reinterpret_cast<__half2*>(Ch + (size_t)row * Nn + col) =
                        __floats2half2_rn(f0, f1);
                } else {
                    f0 += __ldg(bias + col);
                    f1 += __ldg(bias + col + 1);
                    if (MODE == 1) {
                        f0 = (f0 > 0.f) ? (f0 + 1.f) : __expf(f0);
                        f1 = (f1 > 0.f) ? (f1 + 1.f) : __expf(f1);
                    }
                    *reinterpret_cast<float2*>(Cf + (size_t)row * Nn + col) =
                        make_float2(f0, f1);
                }
            }
        }
    }
}

// ---------------------------------------------------------------------------
// zero kernel
// ---------------------------------------------------------------------------
__global__ void zero_kernel(float* __restrict__ p, int n)
{
    int i = blockIdx.x * blockDim.x + threadIdx.x;
    if (i < n) p[i] = 0.f;
}

// ---------------------------------------------------------------------------
// kv[bh][d][e] = sum_n k[bh][n][d] * v[bh][n][e];  ksum[bh][d] = sum_n k
// ---------------------------------------------------------------------------
#define KV_CH 512

__global__ __launch_bounds__(256) void kv_ksum_kernel(
    const float* __restrict__ Km, const float* __restrict__ Vm,
    float* __restrict__ kv, float* __restrict__ ksum)
{
    const int bh = blockIdx.x;
    const int b = bh >> 4, h = bh & 15;
    const int chunk = blockIdx.y;
    const int tid = threadIdx.x;

    __shared__ float sk[8][64];
    __shared__ float sv[8][64];

    const int d  = tid >> 2;
    const int e0 = (tid & 3) * 16;

    float acc[16];
#pragma unroll
    for (int j = 0; j < 16; ++j) acc[j] = 0.f;
    float ks = 0.f;

    const size_t base = ((size_t)b * Nseq + (size_t)chunk * KV_CH) * EMBED + h * HDIM;
    const int r0 = tid >> 6, c0 = tid & 63;
    const int r1 = (tid + 256) >> 6, c1 = tid & 63;

    for (int p = 0; p < KV_CH / 8; ++p) {
        const size_t rb = base + (size_t)p * 8 * EMBED;
        sk[r0][c0] = Km[rb + (size_t)r0 * EMBED + c0];
        sk[r1][c1] = Km[rb + (size_t)r1 * EMBED + c1];
        sv[r0][c0] = Vm[rb + (size_t)r0 * EMBED + c0];
        sv[r1][c1] = Vm[rb + (size_t)r1 * EMBED + c1];
        __syncthreads();
#pragma unroll
        for (int r = 0; r < 8; ++r) {
            const float kd = sk[r][d];
            ks += kd;
#pragma unroll
            for (int j = 0; j < 16; ++j)
                acc[j] = fmaf(kd, sv[r][e0 + j], acc[j]);
        }
        __syncthreads();
    }

    float* kvp = kv + (size_t)bh * (HDIM * HDIM) + d * HDIM + e0;
#pragma unroll
    for (int j = 0; j < 16; ++j) atomicAdd(kvp + j, acc[j]);
    if ((tid & 3) == 0) atomicAdd(ksum + bh * HDIM + d, ks);
}

// ---------------------------------------------------------------------------
// attn: out = (q @ kv) / (q . ksum + 1e-6); writes fp16 for Wo GEMM
// ---------------------------------------------------------------------------
__global__ __launch_bounds__(256) void attn_kernel(
    const float* __restrict__ Qm, const float* __restrict__ kv,
    const float* __restrict__ ksum,
    __half* __restrict__ outH)
{
    const int bh = blockIdx.x;
    const int b = bh >> 4, h = bh & 15;
    const int nt = blockIdx.y;
    const int tid = threadIdx.x;

    __shared__ float kv_s[64][65];
    __shared__ float ks_s[64];
    __shared__ float q_s[128][65];

    for (int i = tid; i < 4096; i += 256)
        kv_s[i >> 6][i & 63] = kv[(size_t)bh * 4096 + i];
    if (tid < 64) ks_s[tid] = ksum[bh * 64 + tid];

    const size_t base = ((size_t)b * Nseq + (size_t)nt * 128) * EMBED + h * HDIM;
    for (int i = tid; i < 128 * 64; i += 256) {
        const int r = i >> 6, c = i & 63;
        q_s[r][c] = Qm[base + (size_t)r * EMBED + c];
    }
    __syncthreads();

    const int t  = tid >> 1;
    const int e0 = (tid & 1) * 32;

    float denom = 0.f;
#pragma unroll
    for (int d2 = 0; d2 < 64; ++d2)
        denom = fmaf(q_s[t][d2], ks_s[d2], denom);
    denom += 1e-6f;

    float acc[32];
#pragma unroll
    for (int j = 0; j < 32; ++j) acc[j] = 0.f;
#pragma unroll 4
    for (int d2 = 0; d2 < 64; ++d2) {
        const float qd = q_s[t][d2];
#pragma unroll
        for (int j = 0; j < 32; ++j)
            acc[j] = fmaf(qd, kv_s[d2][e0 + j], acc[j]);
    }

    const float inv = 1.0f / denom;
    const size_t ob = base + (size_t)t * EMBED + e0;
    __half2* hp = reinterpret_cast<__half2*>(outH + ob);
#pragma unroll
    for (int j = 0; j < 32; j += 2)
        hp[j >> 1] = __floats2half2_rn(acc[j] * inv, acc[j + 1] * inv);
}

// ---------------------------------------------------------------------------
// launch
// ---------------------------------------------------------------------------
extern "C" void kernel_launch(void* const* d_in, const int* in_sizes, int n_in,
                              void* d_out, int out_size)
{
    const float* query   = (const float*)d_in[0];
    const float* key_    = (const float*)d_in[1];
    const float* value   = (const float*)d_in[2];
    const float* Wq_down = (const float*)d_in[3];
    const float* Wq_up   = (const float*)d_in[4];
    const float* bq_up   = (const float*)d_in[5];
    const float* Wk_down = (const float*)d_in[6];
    const float* Wk_up   = (const float*)d_in[7];
    const float* bk_up   = (const float*)d_in[8];
    const float* Wv_down = (const float*)d_in[9];
    const float* Wv_up   = (const float*)d_in[10];
    const float* bv_up   = (const float*)d_in[11];
    const float* Wo      = (const float*)d_in[12];
    const float* bo      = (const float*)d_in[13];
    float* out = (float*)d_out;

    __half *inH, *yH, *atH, *wH;
    float *Q, *K, *V, *KVKS;
    cudaGetSymbolAddress((void**)&inH, g_inH);
    cudaGetSymbolAddress((void**)&yH,  g_yH);
    cudaGetSymbolAddress((void**)&atH, g_atH);
    cudaGetSymbolAddress((void**)&wH,  g_wH);
    cudaGetSymbolAddress((void**)&Q,   g_Q);
    cudaGetSymbolAddress((void**)&K,   g_K);
    cudaGetSymbolAddress((void**)&V,   g_V);
    cudaGetSymbolAddress((void**)&KVKS, g_kvks);
    float* KV = KVKS;
    float* KS = KVKS + KV_ELEMS;

    cudaFuncSetAttribute((const void*)gemm_mma1<0>, cudaFuncAttributeMaxDynamicSharedMemorySize, SMEM_GEMM);
    cudaFuncSetAttribute((const void*)gemm_mma1<1>, cudaFuncAttributeMaxDynamicSharedMemorySize, SMEM_GEMM);
    cudaFuncSetAttribute((const void*)gemm_mma1<2>, cudaFuncAttributeMaxDynamicSharedMemorySize, SMEM_GEMM);

    const dim3 blk(512);
    const dim3 gdown(RANK / 128, MTOK / 256);    // (4, 128)
    const dim3 gup(EMBED / 128, MTOK / 256);     // (8, 128)

    // weight converts
    cvt_kernel<<<(RANK*EMBED/4 + 255)/256, 256>>>(Wq_down, wH + W_QD, RANK*EMBED/4);
    cvt_kernel<<<(EMBED*RANK/4 + 255)/256, 256>>>(Wq_up,   wH + W_QU, EMBED*RANK/4);
    cvt_kernel<<<(RANK*EMBED/4 + 255)/256, 256>>>(Wk_down, wH + W_KD, RANK*EMBED/4);
    cvt_kernel<<<(EMBED*RANK/4 + 255)/256, 256>>>(Wk_up,   wH + W_KU, EMBED*RANK/4);
    cvt_kernel<<<(RANK*EMBED/4 + 255)/256, 256>>>(Wv_down, wH + W_VD, RANK*EMBED/4);
    cvt_kernel<<<(EMBED*RANK/4 + 255)/256, 256>>>(Wv_up,   wH + W_VU, EMBED*RANK/4);
    cvt_kernel<<<(EMBED*EMBED/4 + 255)/256, 256>>>(Wo,     wH + W_O,  EMBED*EMBED/4);

    const int nAct4 = MTOK * EMBED / 4;

    // Q path
    cvt_kernel<<<(nAct4 + 255)/256, 256>>>(query, inH, nAct4);
    gemm_mma1<0><<<gdown, blk, SMEM_GEMM>>>(inH, wH + W_QD, nullptr, nullptr, yH, RANK, EMBED);
    gemm_mma1<1><<<gup, blk, SMEM_GEMM>>>(yH, wH + W_QU, bq_up, Q, nullptr, EMBED, RANK);
    // K path
    cvt_kernel<<<(nAct4 + 255)/256, 256>>>(key_, inH, nAct4);
    gemm_mma1<0><<<gdown, blk, SMEM_GEMM>>>(inH, wH + W_KD, nullptr, nullptr, yH, RANK, EMBED);
    gemm_mma1<1><<<gup, blk, SMEM_GEMM>>>(yH, wH + W_KU, bk_up, K, nullptr, EMBED, RANK);
    // V path
    cvt_kernel<<<(nAct4 + 255)/256, 256>>>(value, inH, nAct4);
    gemm_mma1<0><<<gdown, blk, SMEM_GEMM>>>(inH, wH + W_VD, nullptr, nullptr, yH, RANK, EMBED);
    gemm_mma1<2><<<gup, blk, SMEM_GEMM>>>(yH, wH + W_VU, bv_up, V, nullptr, EMBED, RANK);

    // kv / ksum reduction
    const int nz = KV_ELEMS + KS_ELEMS;
    zero_kernel<<<(nz + 255) / 256, 256>>>(KVKS, nz);
    kv_ksum_kernel<<<dim3(Bv * HEADS, Nseq / KV_CH), dim3(256)>>>(K, V, KV, KS);

    // attention (writes fp16)
    attn_kernel<<<dim3(Bv * HEADS, Nseq / 128), dim3(256)>>>(Q, KV, KS, atH);

    // output projection
    gemm_mma1<2><<<gup, blk, SMEM_GEMM>>>(atH, wH + W_O, bo, out, nullptr, EMBED, EMBED);
}

// round 8
// speedup vs baseline: 3.9735x; 1.1679x over previous
#include <cuda_runtime.h>
#include <cuda_fp16.h>
#include <cstdint>

// ---------------------------------------------------------------------------
// Problem constants
// ---------------------------------------------------------------------------
#define Bv     4
#define Nseq   8192
#define EMBED  1024
#define HEADS  16
#define HDIM   64
#define RANK   512
#define MTOK   (Bv * Nseq)          // 32768

// ---------------------------------------------------------------------------
// Scratch (__device__ globals; allocation forbidden)
// ---------------------------------------------------------------------------
__device__ __half g_inH[MTOK * EMBED];   // fp16 of q/k/v input (reused)
__device__ __half g_yH [MTOK * RANK];    // low-rank intermediate
__device__ __half g_atH[MTOK * EMBED];   // attention output

#define W_QD 0
#define W_QU (W_QD + RANK*EMBED)
#define W_KD (W_QU + EMBED*RANK)
#define W_KU (W_KD + RANK*EMBED)
#define W_VD (W_KU + EMBED*RANK)
#define W_VU (W_VD + RANK*EMBED)
#define W_O  (W_VU + EMBED*RANK)
#define W_TOT (W_O + EMBED*EMBED)
__device__ __half g_wH[W_TOT];

__device__ float g_Q[MTOK * EMBED];
__device__ float g_K[MTOK * EMBED];
__device__ float g_V[MTOK * EMBED];
__device__ float g_kvks[Bv * HEADS * (HDIM * HDIM + HDIM)];
#define KV_ELEMS (Bv * HEADS * HDIM * HDIM)
#define KS_ELEMS (Bv * HEADS * HDIM)

// ---------------------------------------------------------------------------
// helpers
// ---------------------------------------------------------------------------
__device__ __forceinline__ uint32_t smem_u32(const void* p) {
    uint32_t a;
    asm("{ .reg .u64 t; cvta.to.shared.u64 t, %1; cvt.u32.u64 %0, t; }"
        : "=r"(a) : "l"(p));
    return a;
}

__device__ __forceinline__ void ldsm4(uint32_t* r, uint32_t addr) {
    asm volatile("ldmatrix.sync.aligned.m8n8.x4.shared.b16 {%0,%1,%2,%3}, [%4];"
        : "=r"(r[0]), "=r"(r[1]), "=r"(r[2]), "=r"(r[3]) : "r"(addr));
}

__device__ __forceinline__ void mma16816(float* c, const uint32_t* a, const uint32_t* b) {
    asm volatile("mma.sync.aligned.m16n8k16.row.col.f32.f16.f16.f32 "
        "{%0,%1,%2,%3}, {%4,%5,%6,%7}, {%8,%9}, {%0,%1,%2,%3};"
        : "+f"(c[0]), "+f"(c[1]), "+f"(c[2]), "+f"(c[3])
        : "r"(a[0]), "r"(a[1]), "r"(a[2]), "r"(a[3]), "r"(b[0]), "r"(b[1]));
}

#define CP_ASYNC16(so, ga) \
    asm volatile("cp.async.cg.shared.global [%0], [%1], 16;\n" :: "r"(so), "l"(ga))
#define CP_COMMIT() asm volatile("cp.async.commit_group;\n" ::: "memory")
#define CP_WAIT(n)  asm volatile("cp.async.wait_group %0;\n" :: "n"(n) : "memory")

// ---------------------------------------------------------------------------
// convert kernel: fp32 -> fp16
// ---------------------------------------------------------------------------
__global__ void cvt_kernel(const float* __restrict__ x,
                           __half* __restrict__ y, int n4)
{
    int i = blockIdx.x * blockDim.x + threadIdx.x;
    if (i >= n4) return;
    float4 v = reinterpret_cast<const float4*>(x)[i];
    __half2* yp = reinterpret_cast<__half2*>(y);
    yp[2*i]   = __floats2half2_rn(v.x, v.y);
    yp[2*i+1] = __floats2half2_rn(v.z, v.w);
}

// ---------------------------------------------------------------------------
// mma.sync fp16 NT GEMM: C[m,n] = sum_k A[m,k]*B[n,k], fp32 accum.
// Tile 128x128, BK=64, 8 warps (2x4, warp tile 64x32), 3-stage cp.async,
// 2 CTAs/SM. SMEM rows strided 144B (conflict-free ldmatrix).
// MODE 0: fp16 out. MODE 1: fp32 bias+elu+1. MODE 2: fp32 + bias.
// ---------------------------------------------------------------------------
#define BKC        64
#define RSTRIDE_B  144
#define A_TILE_BY  (128 * RSTRIDE_B)        // 18432
#define B_TILE_BY  (128 * RSTRIDE_B)        // 18432
#define STAGE_BY   (A_TILE_BY + B_TILE_BY)  // 36864
#define NSTAGE     3
#define SMEM_GEMM  (NSTAGE * STAGE_BY)      // 110592
#define OFF_A      0
#define OFF_B      A_TILE_BY

__device__ __forceinline__ void load_stage_mma(
    uint32_t sb, int tid, int s, int k0,
    const __half* __restrict__ A, const __half* __restrict__ B,
    int K, int aRow0, int bRow0)
{
    const uint32_t stage = sb + (uint32_t)s * STAGE_BY;
#pragma unroll
    for (int i = 0; i < 8; ++i) {
        int idx = tid + i * 256;            // 0..2047
        int row = (idx & 1023) >> 3;        // 0..127
        int cb  = idx & 7;                  // 16B chunk in 128B row
        const __half* gp;
        int r0;
        uint32_t tbase;
        if (idx < 1024) { gp = A; r0 = aRow0; tbase = OFF_A; }
        else            { gp = B; r0 = bRow0; tbase = OFF_B; }
        const void* ga = gp + (size_t)(r0 + row) * K + k0 + cb * 8;
        uint32_t so = stage + tbase + (uint32_t)row * RSTRIDE_B + cb * 16;
        CP_ASYNC16(so, ga);
    }
    CP_COMMIT();
}

template <int MODE>
__global__ __launch_bounds__(256, 2) void gemm_mma1(
    const __half* __restrict__ A, const __half* __restrict__ B,
    const float* __restrict__ bias, float* __restrict__ Cf,
    __half* __restrict__ Ch,
    int Nn, int K)
{
    extern __shared__ char smem[];
    const uint32_t sb = smem_u32(smem);
    const int tid = threadIdx.x;
    const int wid = tid >> 5;
    const int lane = tid & 31;
    const int bn = blockIdx.x, bm = blockIdx.y;
    const int warp_m = wid >> 2;            // 0..1  (64 rows each)
    const int warp_n = wid & 3;             // 0..3  (32 cols each)
    const int aRow0 = bm * 128, bRow0 = bn * 128;

    float acc[4][4][4];
#pragma unroll
    for (int mt = 0; mt < 4; ++mt)
#pragma unroll
        for (int nt = 0; nt < 4; ++nt)
#pragma unroll
            for (int j = 0; j < 4; ++j) acc[mt][nt][j] = 0.f;

    const int nch = K / BKC;                // 8 or 16

    load_stage_mma(sb, tid, 0, 0,   A, B, K, aRow0, bRow0);
    load_stage_mma(sb, tid, 1, BKC, A, B, K, aRow0, bRow0);

    const int a_r = lane & 15;
    const int a_c = (lane >> 4) * 8;
    const int b_n = ((lane >> 4) << 3) + (lane & 7);
    const int b_k = ((lane >> 3) & 1) * 8;

    for (int c = 0; c < nch; ++c) {
        if (c == nch - 1) { CP_WAIT(0); } else { CP_WAIT(1); }
        __syncthreads();

        if (c + 2 < nch)
            load_stage_mma(sb, tid, (c + 2) % NSTAGE, (c + 2) * BKC,
                           A, B, K, aRow0, bRow0);

        const uint32_t st = sb + (uint32_t)(c % NSTAGE) * STAGE_BY;
#pragma unroll
        for (int ks = 0; ks < 4; ++ks) {
            const int k0 = ks * 16;
            uint32_t ar[4][4];
#pragma unroll
            for (int mt = 0; mt < 4; ++mt) {
                uint32_t off = (uint32_t)(warp_m * 64 + mt * 16 + a_r) * RSTRIDE_B
                             + (uint32_t)(k0 + a_c) * 2;
                ldsm4(ar[mt], st + OFF_A + off);
            }
            uint32_t br[4][2];
#pragma unroll
            for (int nt2 = 0; nt2 < 2; ++nt2) {
                uint32_t off = (uint32_t)(warp_n * 32 + nt2 * 16 + b_n) * RSTRIDE_B
                             + (uint32_t)(k0 + b_k) * 2;
                uint32_t t4[4];
                ldsm4(t4, st + OFF_B + off);
                br[nt2*2][0] = t4[0]; br[nt2*2][1] = t4[1];
                br[nt2*2+1][0] = t4[2]; br[nt2*2+1][1] = t4[3];
            }
#pragma unroll
            for (int mt = 0; mt < 4; ++mt)
#pragma unroll
                for (int nt = 0; nt < 4; ++nt)
                    mma16816(acc[mt][nt], ar[mt], br[nt]);
        }
    }

    // epilogue
#pragma unroll
    for (int mt = 0; mt < 4; ++mt) {
#pragma unroll
        for (int nt = 0; nt < 4; ++nt) {
            const int row0 = bm * 128 + warp_m * 64 + mt * 16 + (lane >> 2);
            const int col  = bn * 128 + warp_n * 32 + nt * 8 + (lane & 3) * 2;
#pragma unroll
            for (int h = 0; h < 2; ++h) {
                const int row = row0 + h * 8;
                float f0 = acc[mt][nt][h * 2 + 0];
                float f1 = acc[mt][nt][h * 2 + 1];
                if (MODE == 0) {
                    *reinterpret_cast<__half2*>(Ch + (size_t)row * Nn + col) =
                        __floats2half2_rn(f0, f1);
                } else {
                    f0 += __ldg(bias + col);
                    f1 += __ldg(bias + col + 1);
                    if (MODE == 1) {
                        f0 = (f0 > 0.f) ? (f0 + 1.f) : __expf(f0);
                        f1 = (f1 > 0.f) ? (f1 + 1.f) : __expf(f1);
                    }
                    *reinterpret_cast<float2*>(Cf + (size_t)row * Nn + col) =
                        make_float2(f0, f1);
                }
            }
        }
    }
}

// ---------------------------------------------------------------------------
// zero kernel
// ---------------------------------------------------------------------------
__global__ void zero_kernel(float* __restrict__ p, int n)
{
    int i = blockIdx.x * blockDim.x + threadIdx.x;
    if (i < n) p[i] = 0.f;
}

// ---------------------------------------------------------------------------
// kv[bh][d][e] = sum_n k[bh][n][d] * v[bh][n][e];  ksum[bh][d] = sum_n k
// ---------------------------------------------------------------------------
#define KV_CH 512

__global__ __launch_bounds__(256) void kv_ksum_kernel(
    const float* __restrict__ Km, const float* __restrict__ Vm,
    float* __restrict__ kv, float* __restrict__ ksum)
{
    const int bh = blockIdx.x;
    const int b = bh >> 4, h = bh & 15;
    const int chunk = blockIdx.y;
    const int tid = threadIdx.x;

    __shared__ float sk[8][64];
    __shared__ float sv[8][64];

    const int d  = tid >> 2;
    const int e0 = (tid & 3) * 16;

    float acc[16];
#pragma unroll
    for (int j = 0; j < 16; ++j) acc[j] = 0.f;
    float ks = 0.f;

    const size_t base = ((size_t)b * Nseq + (size_t)chunk * KV_CH) * EMBED + h * HDIM;
    const int r0 = tid >> 6, c0 = tid & 63;
    const int r1 = (tid + 256) >> 6, c1 = tid & 63;

    for (int p = 0; p < KV_CH / 8; ++p) {
        const size_t rb = base + (size_t)p * 8 * EMBED;
        sk[r0][c0] = Km[rb + (size_t)r0 * EMBED + c0];
        sk[r1][c1] = Km[rb + (size_t)r1 * EMBED + c1];
        sv[r0][c0] = Vm[rb + (size_t)r0 * EMBED + c0];
        sv[r1][c1] = Vm[rb + (size_t)r1 * EMBED + c1];
        __syncthreads();
#pragma unroll
        for (int r = 0; r < 8; ++r) {
            const float kd = sk[r][d];
            ks += kd;
#pragma unroll
            for (int j = 0; j < 16; ++j)
                acc[j] = fmaf(kd, sv[r][e0 + j], acc[j]);
        }
        __syncthreads();
    }

    float* kvp = kv + (size_t)bh * (HDIM * HDIM) + d * HDIM + e0;
#pragma unroll
    for (int j = 0; j < 16; ++j) atomicAdd(kvp + j, acc[j]);
    if ((tid & 3) == 0) atomicAdd(ksum + bh * HDIM + d, ks);
}

// ---------------------------------------------------------------------------
// attn: out = (q @ kv) / (q . ksum + 1e-6); writes fp16 for Wo GEMM
// ---------------------------------------------------------------------------
__global__ __launch_bounds__(256) void attn_kernel(
    const float* __restrict__ Qm, const float* __restrict__ kv,
    const float* __restrict__ ksum,
    __half* __restrict__ outH)
{
    const int bh = blockIdx.x;
    const int b = bh >> 4, h = bh & 15;
    const int nt = blockIdx.y;
    const int tid = threadIdx.x;

    __shared__ float kv_s[64][65];
    __shared__ float ks_s[64];
    __shared__ float q_s[128][65];

    for (int i = tid; i < 4096; i += 256)
        kv_s[i >> 6][i & 63] = kv[(size_t)bh * 4096 + i];
    if (tid < 64) ks_s[tid] = ksum[bh * 64 + tid];

    const size_t base = ((size_t)b * Nseq + (size_t)nt * 128) * EMBED + h * HDIM;
    for (int i = tid; i < 128 * 64; i += 256) {
        const int r = i >> 6, c = i & 63;
        q_s[r][c] = Qm[base + (size_t)r * EMBED + c];
    }
    __syncthreads();

    const int t  = tid >> 1;
    const int e0 = (tid & 1) * 32;

    float denom = 0.f;
#pragma unroll
    for (int d2 = 0; d2 < 64; ++d2)
        denom = fmaf(q_s[t][d2], ks_s[d2], denom);
    denom += 1e-6f;

    float acc[32];
#pragma unroll
    for (int j = 0; j < 32; ++j) acc[j] = 0.f;
#pragma unroll 4
    for (int d2 = 0; d2 < 64; ++d2) {
        const float qd = q_s[t][d2];
#pragma unroll
        for (int j = 0; j < 32; ++j)
            acc[j] = fmaf(qd, kv_s[d2][e0 + j], acc[j]);
    }

    const float inv = 1.0f / denom;
    const size_t ob = base + (size_t)t * EMBED + e0;
    __half2* hp = reinterpret_cast<__half2*>(outH + ob);
#pragma unroll
    for (int j = 0; j < 32; j += 2)
        hp[j >> 1] = __floats2half2_rn(acc[j] * inv, acc[j + 1] * inv);
}

// ---------------------------------------------------------------------------
// launch
// ---------------------------------------------------------------------------
extern "C" void kernel_launch(void* const* d_in, const int* in_sizes, int n_in,
                              void* d_out, int out_size)
{
    const float* query   = (const float*)d_in[0];
    const float* key_    = (const float*)d_in[1];
    const float* value   = (const float*)d_in[2];
    const float* Wq_down = (const float*)d_in[3];
    const float* Wq_up   = (const float*)d_in[4];
    const float* bq_up   = (const float*)d_in[5];
    const float* Wk_down = (const float*)d_in[6];
    const float* Wk_up   = (const float*)d_in[7];
    const float* bk_up   = (const float*)d_in[8];
    const float* Wv_down = (const float*)d_in[9];
    const float* Wv_up   = (const float*)d_in[10];
    const float* bv_up   = (const float*)d_in[11];
    const float* Wo      = (const float*)d_in[12];
    const float* bo      = (const float*)d_in[13];
    float* out = (float*)d_out;

    __half *inH, *yH, *atH, *wH;
    float *Q, *K, *V, *KVKS;
    cudaGetSymbolAddress((void**)&inH, g_inH);
    cudaGetSymbolAddress((void**)&yH,  g_yH);
    cudaGetSymbolAddress((void**)&atH, g_atH);
    cudaGetSymbolAddress((void**)&wH,  g_wH);
    cudaGetSymbolAddress((void**)&Q,   g_Q);
    cudaGetSymbolAddress((void**)&K,   g_K);
    cudaGetSymbolAddress((void**)&V,   g_V);
    cudaGetSymbolAddress((void**)&KVKS, g_kvks);
    float* KV = KVKS;
    float* KS = KVKS + KV_ELEMS;

    cudaFuncSetAttribute((const void*)gemm_mma1<0>, cudaFuncAttributeMaxDynamicSharedMemorySize, SMEM_GEMM);
    cudaFuncSetAttribute((const void*)gemm_mma1<1>, cudaFuncAttributeMaxDynamicSharedMemorySize, SMEM_GEMM);
    cudaFuncSetAttribute((const void*)gemm_mma1<2>, cudaFuncAttributeMaxDynamicSharedMemorySize, SMEM_GEMM);

    const dim3 blk(256);
    const dim3 gdown(RANK / 128, MTOK / 128);    // (4, 256)
    const dim3 gup(EMBED / 128, MTOK / 128);     // (8, 256)

    // weight converts
    cvt_kernel<<<(RANK*EMBED/4 + 255)/256, 256>>>(Wq_down, wH + W_QD, RANK*EMBED/4);
    cvt_kernel<<<(EMBED*RANK/4 + 255)/256, 256>>>(Wq_up,   wH + W_QU, EMBED*RANK/4);
    cvt_kernel<<<(RANK*EMBED/4 + 255)/256, 256>>>(Wk_down, wH + W_KD, RANK*EMBED/4);
    cvt_kernel<<<(EMBED*RANK/4 + 255)/256, 256>>>(Wk_up,   wH + W_KU, EMBED*RANK/4);
    cvt_kernel<<<(RANK*EMBED/4 + 255)/256, 256>>>(Wv_down, wH + W_VD, RANK*EMBED/4);
    cvt_kernel<<<(EMBED*RANK/4 + 255)/256, 256>>>(Wv_up,   wH + W_VU, EMBED*RANK/4);
    cvt_kernel<<<(EMBED*EMBED/4 + 255)/256, 256>>>(Wo,     wH + W_O,  EMBED*EMBED/4);

    const int nAct4 = MTOK * EMBED / 4;

    // Q path
    cvt_kernel<<<(nAct4 + 255)/256, 256>>>(query, inH, nAct4);
    gemm_mma1<0><<<gdown, blk, SMEM_GEMM>>>(inH, wH + W_QD, nullptr, nullptr, yH, RANK, EMBED);
    gemm_mma1<1><<<gup, blk, SMEM_GEMM>>>(yH, wH + W_QU, bq_up, Q, nullptr, EMBED, RANK);
    // K path
    cvt_kernel<<<(nAct4 + 255)/256, 256>>>(key_, inH, nAct4);
    gemm_mma1<0><<<gdown, blk, SMEM_GEMM>>>(inH, wH + W_KD, nullptr, nullptr, yH, RANK, EMBED);
    gemm_mma1<1><<<gup, blk, SMEM_GEMM>>>(yH, wH + W_KU, bk_up, K, nullptr, EMBED, RANK);
    // V path
    cvt_kernel<<<(nAct4 + 255)/256, 256>>>(value, inH, nAct4);
    gemm_mma1<0><<<gdown, blk, SMEM_GEMM>>>(inH, wH + W_VD, nullptr, nullptr, yH, RANK, EMBED);
    gemm_mma1<2><<<gup, blk, SMEM_GEMM>>>(yH, wH + W_VU, bv_up, V, nullptr, EMBED, RANK);

    // kv / ksum reduction
    const int nz = KV_ELEMS + KS_ELEMS;
    zero_kernel<<<(nz + 255) / 256, 256>>>(KVKS, nz);
    kv_ksum_kernel<<<dim3(Bv * HEADS, Nseq / KV_CH), dim3(256)>>>(K, V, KV, KS);

    // attention (writes fp16)
    attn_kernel<<<dim3(Bv * HEADS, Nseq / 128), dim3(256)>>>(Q, KV, KS, atH);

    // output projection
    gemm_mma1<2><<<gup, blk, SMEM_GEMM>>>(atH, wH + W_O, bo, out, nullptr, EMBED, EMBED);
}

// round 9
// speedup vs baseline: 4.4818x; 1.1279x over previous
#include <cuda_runtime.h>
#include <cuda_fp16.h>
#include <cstdint>

// ---------------------------------------------------------------------------
// Problem constants
// ---------------------------------------------------------------------------
#define Bv     4
#define Nseq   8192
#define EMBED  1024
#define HEADS  16
#define HDIM   64
#define RANK   512
#define MTOK   (Bv * Nseq)          // 32768
#define BH     (Bv * HEADS)         // 64

// ---------------------------------------------------------------------------
// Scratch (__device__ globals; allocation forbidden)
// ---------------------------------------------------------------------------
__device__ __half g_inH[MTOK * EMBED];
__device__ __half g_yH [MTOK * RANK];
__device__ __half g_QH [MTOK * EMBED];
__device__ __half g_KH [MTOK * EMBED];
__device__ __half g_VH [MTOK * EMBED];
__device__ __half g_atH[MTOK * EMBED];

#define W_QD 0
#define W_QU (W_QD + RANK*EMBED)
#define W_KD (W_QU + EMBED*RANK)
#define W_KU (W_KD + RANK*EMBED)
#define W_VD (W_KU + EMBED*RANK)
#define W_VU (W_VD + RANK*EMBED)
#define W_O  (W_VU + EMBED*RANK)
#define W_TOT (W_O + EMBED*EMBED)
__device__ __half g_wH[W_TOT];

#define KV_ELEMS (BH * HDIM * HDIM)     // 262144
#define KS_ELEMS (BH * HDIM)            // 4096
__device__ float  g_kvks[KV_ELEMS + KS_ELEMS];
__device__ __half g_kvTh[KV_ELEMS];     // kvT[bh][e][d] fp16
__device__ float  g_dinv[BH * Nseq];    // 1/(denom)

// ---------------------------------------------------------------------------
// helpers
// ---------------------------------------------------------------------------
__device__ __forceinline__ uint32_t smem_u32(const void* p) {
    uint32_t a;
    asm("{ .reg .u64 t; cvta.to.shared.u64 t, %1; cvt.u32.u64 %0, t; }"
        : "=r"(a) : "l"(p));
    return a;
}

__device__ __forceinline__ void ldsm4(uint32_t* r, uint32_t addr) {
    asm volatile("ldmatrix.sync.aligned.m8n8.x4.shared.b16 {%0,%1,%2,%3}, [%4];"
        : "=r"(r[0]), "=r"(r[1]), "=r"(r[2]), "=r"(r[3]) : "r"(addr));
}

__device__ __forceinline__ void mma16816(float* c, const uint32_t* a, const uint32_t* b) {
    asm volatile("mma.sync.aligned.m16n8k16.row.col.f32.f16.f16.f32 "
        "{%0,%1,%2,%3}, {%4,%5,%6,%7}, {%8,%9}, {%0,%1,%2,%3};"
        : "+f"(c[0]), "+f"(c[1]), "+f"(c[2]), "+f"(c[3])
        : "r"(a[0]), "r"(a[1]), "r"(a[2]), "r"(a[3]), "r"(b[0]), "r"(b[1]));
}

#define CP_ASYNC16(so, ga) \
    asm volatile("cp.async.cg.shared.global [%0], [%1], 16;\n" :: "r"(so), "l"(ga))
#define CP_COMMIT() asm volatile("cp.async.commit_group;\n" ::: "memory")
#define CP_WAIT(n)  asm volatile("cp.async.wait_group %0;\n" :: "n"(n) : "memory")

// ---------------------------------------------------------------------------
// convert kernel: fp32 -> fp16
// ---------------------------------------------------------------------------
__global__ void cvt_kernel(const float* __restrict__ x,
                           __half* __restrict__ y, int n4)
{
    int i = blockIdx.x * blockDim.x + threadIdx.x;
    if (i >= n4) return;
    float4 v = reinterpret_cast<const float4*>(x)[i];
    __half2* yp = reinterpret_cast<__half2*>(y);
    yp[2*i]   = __floats2half2_rn(v.x, v.y);
    yp[2*i+1] = __floats2half2_rn(v.z, v.w);
}

// ---------------------------------------------------------------------------
// mma.sync fp16 NT GEMM. Tile 128x128, BK=64, 8 warps, 3-stage, 2 CTAs/SM.
// MODE 0: fp16 out. MODE 1: fp16 bias+elu+1. MODE 2: fp16 + bias. MODE 3: fp32 + bias.
// ---------------------------------------------------------------------------
#define BKC        64
#define RSTRIDE_B  144
#define A_TILE_BY  (128 * RSTRIDE_B)
#define B_TILE_BY  (128 * RSTRIDE_B)
#define STAGE_BY   (A_TILE_BY + B_TILE_BY)  // 36864
#define NSTAGE     3
#define SMEM_GEMM  (NSTAGE * STAGE_BY)      // 110592
#define OFF_A      0
#define OFF_B      A_TILE_BY

__device__ __forceinline__ void load_stage_mma(
    uint32_t sb, int tid, int s, int k0,
    const __half* __restrict__ A, const __half* __restrict__ B,
    int K, int aRow0, int bRow0)
{
    const uint32_t stage = sb + (uint32_t)s * STAGE_BY;
#pragma unroll
    for (int i = 0; i < 8; ++i) {
        int idx = tid + i * 256;
        int row = (idx & 1023) >> 3;
        int cb  = idx & 7;
        const __half* gp;
        int r0;
        uint32_t tbase;
        if (idx < 1024) { gp = A; r0 = aRow0; tbase = OFF_A; }
        else            { gp = B; r0 = bRow0; tbase = OFF_B; }
        const void* ga = gp + (size_t)(r0 + row) * K + k0 + cb * 8;
        uint32_t so = stage + tbase + (uint32_t)row * RSTRIDE_B + cb * 16;
        CP_ASYNC16(so, ga);
    }
    CP_COMMIT();
}

template <int MODE>
__global__ __launch_bounds__(256, 2) void gemm_mma1(
    const __half* __restrict__ A, const __half* __restrict__ B,
    const float* __restrict__ bias, float* __restrict__ Cf,
    __half* __restrict__ Ch,
    int Nn, int K)
{
    extern __shared__ char smem[];
    const uint32_t sb = smem_u32(smem);
    const int tid = threadIdx.x;
    const int wid = tid >> 5;
    const int lane = tid & 31;
    const int bn = blockIdx.x, bm = blockIdx.y;
    const int warp_m = wid >> 2;
    const int warp_n = wid & 3;
    const int aRow0 = bm * 128, bRow0 = bn * 128;

    float acc[4][4][4];
#pragma unroll
    for (int mt = 0; mt < 4; ++mt)
#pragma unroll
        for (int nt = 0; nt < 4; ++nt)
#pragma unroll
            for (int j = 0; j < 4; ++j) acc[mt][nt][j] = 0.f;

    const int nch = K / BKC;

    load_stage_mma(sb, tid, 0, 0,   A, B, K, aRow0, bRow0);
    load_stage_mma(sb, tid, 1, BKC, A, B, K, aRow0, bRow0);

    const int a_r = lane & 15;
    const int a_c = (lane >> 4) * 8;
    const int b_n = ((lane >> 4) << 3) + (lane & 7);
    const int b_k = ((lane >> 3) & 1) * 8;

    for (int c = 0; c < nch; ++c) {
        if (c == nch - 1) { CP_WAIT(0); } else { CP_WAIT(1); }
        __syncthreads();

        if (c + 2 < nch)
            load_stage_mma(sb, tid, (c + 2) % NSTAGE, (c + 2) * BKC,
                           A, B, K, aRow0, bRow0);

        const uint32_t st = sb + (uint32_t)(c % NSTAGE) * STAGE_BY;
#pragma unroll
        for (int ks = 0; ks < 4; ++ks) {
            const int k0 = ks * 16;
            uint32_t ar[4][4];
#pragma unroll
            for (int mt = 0; mt < 4; ++mt) {
                uint32_t off = (uint32_t)(warp_m * 64 + mt * 16 + a_r) * RSTRIDE_B
                             + (uint32_t)(k0 + a_c) * 2;
                ldsm4(ar[mt], st + OFF_A + off);
            }
            uint32_t br[4][2];
#pragma unroll
            for (int nt2 = 0; nt2 < 2; ++nt2) {
                uint32_t off = (uint32_t)(warp_n * 32 + nt2 * 16 + b_n) * RSTRIDE_B
                             + (uint32_t)(k0 + b_k) * 2;
                uint32_t t4[4];
                ldsm4(t4, st + OFF_B + off);
                br[nt2*2][0] = t4[0]; br[nt2*2][1] = t4[1];
                br[nt2*2+1][0] = t4[2]; br[nt2*2+1][1] = t4[3];
            }
#pragma unroll
            for (int mt = 0; mt < 4; ++mt)
#pragma unroll
                for (int nt = 0; nt < 4; ++nt)
                    mma16816(acc[mt][nt], ar[mt], br[nt]);
        }
    }

    // epilogue
#pragma unroll
    for (int mt = 0; mt < 4; ++mt) {
#pragma unroll
        for (int nt = 0; nt < 4; ++nt) {
            const int row0 = bm * 128 + warp_m * 64 + mt * 16 + (lane >> 2);
            const int col  = bn * 128 + warp_n * 32 + nt * 8 + (lane & 3) * 2;
#pragma unroll
            for (int h = 0; h < 2; ++h) {
                const int row = row0 + h * 8;
                float f0 = acc[mt][nt][h * 2 + 0];
                float f1 = acc[mt][nt][h * 2 + 1];
                if (MODE >= 1) {
                    f0 += __ldg(bias + col);
                    f1 += __ldg(bias + col + 1);
                }
                if (MODE == 1) {
                    f0 = (f0 > 0.f) ? (f0 + 1.f) : __expf(f0);
                    f1 = (f1 > 0.f) ? (f1 + 1.f) : __expf(f1);
                }
                if (MODE == 3) {
                    *reinterpret_cast<float2*>(Cf + (size_t)row * Nn + col) =
                        make_float2(f0, f1);
                } else {
                    *reinterpret_cast<__half2*>(Ch + (size_t)row * Nn + col) =
                        __floats2half2_rn(f0, f1);
                }
            }
        }
    }
}

// ---------------------------------------------------------------------------
// zero kernel
// ---------------------------------------------------------------------------
__global__ void zero_kernel(float* __restrict__ p, int n)
{
    int i = blockIdx.x * blockDim.x + threadIdx.x;
    if (i < n) p[i] = 0.f;
}

// ---------------------------------------------------------------------------
// kv[bh][d][e] = sum_n k[n,d]*v[n,e];  ksum[bh][d] = sum_n k   (fp16 in, fp32 math)
// ---------------------------------------------------------------------------
#define KV_CH 512

__global__ __launch_bounds__(256) void kv_ksum_kernel(
    const __half* __restrict__ Km, const __half* __restrict__ Vm,
    float* __restrict__ kv, float* __restrict__ ksum)
{
    const int bh = blockIdx.x;
    const int b = bh >> 4, h = bh & 15;
    const int chunk = blockIdx.y;
    const int tid = threadIdx.x;

    __shared__ float sk[8][64];
    __shared__ float sv[8][64];

    const int d  = tid >> 2;
    const int e0 = (tid & 3) * 16;

    float acc[16];
#pragma unroll
    for (int j = 0; j < 16; ++j) acc[j] = 0.f;
    float ks = 0.f;

    const size_t base = ((size_t)b * Nseq + (size_t)chunk * KV_CH) * EMBED + h * HDIM;
    const int r0 = tid >> 6, c0 = tid & 63;
    const int r1 = (tid + 256) >> 6, c1 = tid & 63;

    for (int p = 0; p < KV_CH / 8; ++p) {
        const size_t rb = base + (size_t)p * 8 * EMBED;
        sk[r0][c0] = __half2float(Km[rb + (size_t)r0 * EMBED + c0]);
        sk[r1][c1] = __half2float(Km[rb + (size_t)r1 * EMBED + c1]);
        sv[r0][c0] = __half2float(Vm[rb + (size_t)r0 * EMBED + c0]);
        sv[r1][c1] = __half2float(Vm[rb + (size_t)r1 * EMBED + c1]);
        __syncthreads();
#pragma unroll
        for (int r = 0; r < 8; ++r) {
            const float kd = sk[r][d];
            ks += kd;
#pragma unroll
            for (int j = 0; j < 16; ++j)
                acc[j] = fmaf(kd, sv[r][e0 + j], acc[j]);
        }
        __syncthreads();
    }

    float* kvp = kv + (size_t)bh * (HDIM * HDIM) + d * HDIM + e0;
#pragma unroll
    for (int j = 0; j < 16; ++j) atomicAdd(kvp + j, acc[j]);
    if ((tid & 3) == 0) atomicAdd(ksum + bh * HDIM + d, ks);
}

// ---------------------------------------------------------------------------
// kvT convert: kv[bh][d][e] fp32 -> kvTh[bh][e][d] fp16
// ---------------------------------------------------------------------------
__global__ __launch_bounds__(256) void kvT_cvt_kernel(
    const float* __restrict__ kv, __half* __restrict__ kvTh)
{
    const int bh = blockIdx.x;
    const int tid = threadIdx.x;
    __shared__ float s[64][65];
    for (int i = tid; i < 4096; i += 256)
        s[i >> 6][i & 63] = kv[(size_t)bh * 4096 + i];
    __syncthreads();
    for (int i = tid; i < 4096; i += 256) {
        const int e = i >> 6, d = i & 63;
        kvTh[(size_t)bh * 4096 + i] = __float2half(s[d][e]);
    }
}

// ---------------------------------------------------------------------------
// denom: dinv[bh][n] = 1 / (q[bh,n,:].ksum[bh,:] + 1e-6)
// ---------------------------------------------------------------------------
__global__ __launch_bounds__(256) void denom_kernel(
    const __half* __restrict__ Qh, const float* __restrict__ ksum,
    float* __restrict__ dinv)
{
    const int bh = blockIdx.y;
    const int b = bh >> 4, h = bh & 15;
    const int tok = blockIdx.x * 256 + threadIdx.x;

    __shared__ float ks_s[64];
    if (threadIdx.x < 64) ks_s[threadIdx.x] = ksum[bh * 64 + threadIdx.x];
    __syncthreads();

    const __half2* qp = reinterpret_cast<const __half2*>(
        Qh + ((size_t)b * Nseq + tok) * EMBED + h * HDIM);
    float d = 0.f;
#pragma unroll
    for (int j = 0; j < 32; ++j) {
        float2 q2 = __half22float2(qp[j]);
        d = fmaf(q2.x, ks_s[2 * j], d);
        d = fmaf(q2.y, ks_s[2 * j + 1], d);
    }
    dinv[(size_t)bh * Nseq + tok] = 1.0f / (d + 1e-6f);
}

// ---------------------------------------------------------------------------
// attn numerator via MMA: atH[b,tok,h*64+e] = (Q[tok,:] @ kvT[e,:]) * dinv
// Per block: one bh, 128 tokens. 8 warps = 4(m) x 2(n), warp tile 32x32.
// ---------------------------------------------------------------------------
#define AT_STR 144
__global__ __launch_bounds__(256) void attn_mma_kernel(
    const __half* __restrict__ Qh, const __half* __restrict__ kvTh,
    const float* __restrict__ dinv, __half* __restrict__ atH)
{
    __shared__ char smem[128 * AT_STR + 64 * AT_STR];
    const uint32_t sq = smem_u32(smem);
    const uint32_t skt = sq + 128 * AT_STR;

    const int bh = blockIdx.x;
    const int b = bh >> 4, h = bh & 15;
    const int tt = blockIdx.y;             // token tile (128)
    const int tid = threadIdx.x;
    const int wid = tid >> 5;
    const int lane = tid & 31;
    const int warp_m = wid >> 1;           // 0..3 (32 rows each)
    const int warp_n = wid & 1;            // 0..1 (32 cols each)

    // load Q tile [128 x 64] fp16
#pragma unroll
    for (int i = 0; i < 4; ++i) {
        int idx = tid + i * 256;           // 0..1023
        int row = idx >> 3, cb = idx & 7;
        const void* ga = Qh + ((size_t)b * Nseq + tt * 128 + row) * EMBED + h * HDIM + cb * 8;
        CP_ASYNC16(sq + (uint32_t)row * AT_STR + cb * 16, ga);
    }
    // load kvT [64 x 64] fp16
#pragma unroll
    for (int i = 0; i < 2; ++i) {
        int idx = tid + i * 256;           // 0..511
        int row = idx >> 3, cb = idx & 7;
        const void* ga = kvTh + (size_t)bh * 4096 + row * 64 + cb * 8;
        CP_ASYNC16(skt + (uint32_t)row * AT_STR + cb * 16, ga);
    }
    CP_COMMIT();
    CP_WAIT(0);
    __syncthreads();

    const int a_r = lane & 15;
    const int a_c = (lane >> 4) * 8;
    const int b_n = ((lane >> 4) << 3) + (lane & 7);
    const int b_k = ((lane >> 3) & 1) * 8;

    float acc[2][4][4];
#pragma unroll
    for (int mt = 0; mt < 2; ++mt)
#pragma unroll
        for (int nt = 0; nt < 4; ++nt)
#pragma unroll
            for (int j = 0; j < 4; ++j) acc[mt][nt][j] = 0.f;

#pragma unroll
    for (int ks = 0; ks < 4; ++ks) {
        const int k0 = ks * 16;
        uint32_t ar[2][4];
#pragma unroll
        for (int mt = 0; mt < 2; ++mt) {
            uint32_t off = (uint32_t)(warp_m * 32 + mt * 16 + a_r) * AT_STR
                         + (uint32_t)(k0 + a_c) * 2;
            ldsm4(ar[mt], sq + off);
        }
        uint32_t br[4][2];
#pragma unroll
        for (int nt2 = 0; nt2 < 2; ++nt2) {
            uint32_t off = (uint32_t)(warp_n * 32 + nt2 * 16 + b_n) * AT_STR
                         + (uint32_t)(k0 + b_k) * 2;
            uint32_t t4[4];
            ldsm4(t4, skt + off);
            br[nt2*2][0] = t4[0]; br[nt2*2][1] = t4[1];
            br[nt2*2+1][0] = t4[2]; br[nt2*2+1][1] = t4[3];
        }
#pragma unroll
        for (int mt = 0; mt < 2; ++mt)
#pragma unroll
            for (int nt = 0; nt < 4; ++nt)
                mma16816(acc[mt][nt], ar[mt], br[nt]);
    }

    // epilogue: multiply by dinv, write fp16
#pragma unroll
    for (int mt = 0; mt < 2; ++mt) {
#pragma unroll
        for (int hh = 0; hh < 2; ++hh) {
            const int rloc = warp_m * 32 + mt * 16 + (lane >> 2) + hh * 8;
            const float dv = __ldg(dinv + (size_t)bh * Nseq + tt * 128 + rloc);
            const size_t ob = ((size_t)b * Nseq + tt * 128 + rloc) * EMBED + h * HDIM;
#pragma unroll
            for (int nt = 0; nt < 4; ++nt) {
                const int col = warp_n * 32 + nt * 8 + (lane & 3) * 2;
                float f0 = acc[mt][nt][hh * 2 + 0] * dv;
                float f1 = acc[mt][nt][hh * 2 + 1] * dv;
                *reinterpret_cast<__half2*>(atH + ob + col) = __floats2half2_rn(f0, f1);
            }
        }
    }
}

// ---------------------------------------------------------------------------
// launch
// ---------------------------------------------------------------------------
extern "C" void kernel_launch(void* const* d_in, const int* in_sizes, int n_in,
                              void* d_out, int out_size)
{
    const float* query   = (const float*)d_in[0];
    const float* key_    = (const float*)d_in[1];
    const float* value   = (const float*)d_in[2];
    const float* Wq_down = (const float*)d_in[3];
    const float* Wq_up   = (const float*)d_in[4];
    const float* bq_up   = (const float*)d_in[5];
    const float* Wk_down = (const float*)d_in[6];
    const float* Wk_up   = (const float*)d_in[7];
    const float* bk_up   = (const float*)d_in[8];
    const float* Wv_down = (const float*)d_in[9];
    const float* Wv_up   = (const float*)d_in[10];
    const float* bv_up   = (const float*)d_in[11];
    const float* Wo      = (const float*)d_in[12];
    const float* bo      = (const float*)d_in[13];
    float* out = (float*)d_out;

    __half *inH, *yH, *QH, *KH, *VH, *atH, *wH, *kvTh;
    float *KVKS, *DINV;
    cudaGetSymbolAddress((void**)&inH,  g_inH);
    cudaGetSymbolAddress((void**)&yH,   g_yH);
    cudaGetSymbolAddress((void**)&QH,   g_QH);
    cudaGetSymbolAddress((void**)&KH,   g_KH);
    cudaGetSymbolAddress((void**)&VH,   g_VH);
    cudaGetSymbolAddress((void**)&atH,  g_atH);
    cudaGetSymbolAddress((void**)&wH,   g_wH);
    cudaGetSymbolAddress((void**)&kvTh, g_kvTh);
    cudaGetSymbolAddress((void**)&KVKS, g_kvks);
    cudaGetSymbolAddress((void**)&DINV, g_dinv);
    float* KV = KVKS;
    float* KS = KVKS + KV_ELEMS;

    cudaFuncSetAttribute((const void*)gemm_mma1<0>, cudaFuncAttributeMaxDynamicSharedMemorySize, SMEM_GEMM);
    cudaFuncSetAttribute((const void*)gemm_mma1<1>, cudaFuncAttributeMaxDynamicSharedMemorySize, SMEM_GEMM);
    cudaFuncSetAttribute((const void*)gemm_mma1<2>, cudaFuncAttributeMaxDynamicSharedMemorySize, SMEM_GEMM);
    cudaFuncSetAttribute((const void*)gemm_mma1<3>, cudaFuncAttributeMaxDynamicSharedMemorySize, SMEM_GEMM);

    const dim3 blk(256);
    const dim3 gdown(RANK / 128, MTOK / 128);    // (4, 256)
    const dim3 gup(EMBED / 128, MTOK / 128);     // (8, 256)

    // weight converts
    cvt_kernel<<<(RANK*EMBED/4 + 255)/256, 256>>>(Wq_down, wH + W_QD, RANK*EMBED/4);
    cvt_kernel<<<(EMBED*RANK/4 + 255)/256, 256>>>(Wq_up,   wH + W_QU, EMBED*RANK/4);
    cvt_kernel<<<(RANK*EMBED/4 + 255)/256, 256>>>(Wk_down, wH + W_KD, RANK*EMBED/4);
    cvt_kernel<<<(EMBED*RANK/4 + 255)/256, 256>>>(Wk_up,   wH + W_KU, EMBED*RANK/4);
    cvt_kernel<<<(RANK*EMBED/4 + 255)/256, 256>>>(Wv_down, wH + W_VD, RANK*EMBED/4);
    cvt_kernel<<<(EMBED*RANK/4 + 255)/256, 256>>>(Wv_up,   wH + W_VU, EMBED*RANK/4);
    cvt_kernel<<<(EMBED*EMBED/4 + 255)/256, 256>>>(Wo,     wH + W_O,  EMBED*EMBED/4);

    const int nAct4 = MTOK * EMBED / 4;

    // Q path
    cvt_kernel<<<(nAct4 + 255)/256, 256>>>(query, inH, nAct4);
    gemm_mma1<0><<<gdown, blk, SMEM_GEMM>>>(inH, wH + W_QD, nullptr, nullptr, yH, RANK, EMBED);
    gemm_mma1<1><<<gup, blk, SMEM_GEMM>>>(yH, wH + W_QU, bq_up, nullptr, QH, EMBED, RANK);
    // K path
    cvt_kernel<<<(nAct4 + 255)/256, 256>>>(key_, inH, nAct4);
    gemm_mma1<0><<<gdown, blk, SMEM_GEMM>>>(inH, wH + W_KD, nullptr, nullptr, yH, RANK, EMBED);
    gemm_mma1<1><<<gup, blk, SMEM_GEMM>>>(yH, wH + W_KU, bk_up, nullptr, KH, EMBED, RANK);
    // V path
    cvt_kernel<<<(nAct4 + 255)/256, 256>>>(value, inH, nAct4);
    gemm_mma1<0><<<gdown, blk, SMEM_GEMM>>>(inH, wH + W_VD, nullptr, nullptr, yH, RANK, EMBED);
    gemm_mma1<2><<<gup, blk, SMEM_GEMM>>>(yH, wH + W_VU, bv_up, nullptr, VH, EMBED, RANK);

    // kv / ksum
    const int nz = KV_ELEMS + KS_ELEMS;
    zero_kernel<<<(nz + 255) / 256, 256>>>(KVKS, nz);
    kv_ksum_kernel<<<dim3(BH, Nseq / KV_CH), dim3(256)>>>(KH, VH, KV, KS);
    kvT_cvt_kernel<<<BH, 256>>>(KV, kvTh);
    denom_kernel<<<dim3(Nseq / 256, BH), dim3(256)>>>(QH, KS, DINV);

    // attention numerator (MMA) + divide
    attn_mma_kernel<<<dim3(BH, Nseq / 128), dim3(256)>>>(QH, kvTh, DINV, atH);

    // output projection (fp32 out)
    gemm_mma1<3><<<gup, blk, SMEM_GEMM>>>(atH, wH + W_O, bo, out, nullptr, EMBED, EMBED);
}

// round 10
// speedup vs baseline: 6.2291x; 1.3899x over previous
#include <cuda_runtime.h>
#include <cuda_fp16.h>
#include <cstdint>

// ---------------------------------------------------------------------------
// Problem constants
// ---------------------------------------------------------------------------
#define Bv     4
#define Nseq   8192
#define EMBED  1024
#define HEADS  16
#define HDIM   64
#define RANK   512
#define MTOK   (Bv * Nseq)          // 32768
#define BH     (Bv * HEADS)         // 64

// ---------------------------------------------------------------------------
// Scratch (__device__ globals; allocation forbidden)
// ---------------------------------------------------------------------------
__device__ __half g_inH[MTOK * EMBED];
__device__ __half g_yH [MTOK * RANK];
__device__ __half g_QH [MTOK * EMBED];
__device__ __half g_KH [MTOK * EMBED];
__device__ __half g_VH [MTOK * EMBED];
__device__ __half g_atH[MTOK * EMBED];

#define W_QD 0
#define W_QU (W_QD + RANK*EMBED)
#define W_KD (W_QU + EMBED*RANK)
#define W_KU (W_KD + RANK*EMBED)
#define W_VD (W_KU + EMBED*RANK)
#define W_VU (W_VD + RANK*EMBED)
#define W_O  (W_VU + EMBED*RANK)
#define W_TOT (W_O + EMBED*EMBED)
__device__ __half g_wH[W_TOT];

#define KV_ELEMS (BH * HDIM * HDIM)     // 262144
#define KS_ELEMS (BH * HDIM)            // 4096
__device__ float  g_kvks[KV_ELEMS + KS_ELEMS];
__device__ __half g_kvTh[KV_ELEMS];     // kvT[bh][e][d] fp16
__device__ float  g_dinv[BH * Nseq];

// ---------------------------------------------------------------------------
// helpers
// ---------------------------------------------------------------------------
__device__ __forceinline__ uint32_t smem_u32(const void* p) {
    uint32_t a;
    asm("{ .reg .u64 t; cvta.to.shared.u64 t, %1; cvt.u32.u64 %0, t; }"
        : "=r"(a) : "l"(p));
    return a;
}

__device__ __forceinline__ void ldsm4(uint32_t* r, uint32_t addr) {
    asm volatile("ldmatrix.sync.aligned.m8n8.x4.shared.b16 {%0,%1,%2,%3}, [%4];"
        : "=r"(r[0]), "=r"(r[1]), "=r"(r[2]), "=r"(r[3]) : "r"(addr));
}

__device__ __forceinline__ void ldsm4t(uint32_t* r, uint32_t addr) {
    asm volatile("ldmatrix.sync.aligned.m8n8.x4.trans.shared.b16 {%0,%1,%2,%3}, [%4];"
        : "=r"(r[0]), "=r"(r[1]), "=r"(r[2]), "=r"(r[3]) : "r"(addr));
}

__device__ __forceinline__ void mma16816(float* c, const uint32_t* a, const uint32_t* b) {
    asm volatile("mma.sync.aligned.m16n8k16.row.col.f32.f16.f16.f32 "
        "{%0,%1,%2,%3}, {%4,%5,%6,%7}, {%8,%9}, {%0,%1,%2,%3};"
        : "+f"(c[0]), "+f"(c[1]), "+f"(c[2]), "+f"(c[3])
        : "r"(a[0]), "r"(a[1]), "r"(a[2]), "r"(a[3]), "r"(b[0]), "r"(b[1]));
}

#define CP_ASYNC16(so, ga) \
    asm volatile("cp.async.cg.shared.global [%0], [%1], 16;\n" :: "r"(so), "l"(ga))
#define CP_COMMIT() asm volatile("cp.async.commit_group;\n" ::: "memory")
#define CP_WAIT(n)  asm volatile("cp.async.wait_group %0;\n" :: "n"(n) : "memory")

// ---------------------------------------------------------------------------
// convert kernel: fp32 -> fp16
// ---------------------------------------------------------------------------
__global__ void cvt_kernel(const float* __restrict__ x,
                           __half* __restrict__ y, int n4)
{
    int i = blockIdx.x * blockDim.x + threadIdx.x;
    if (i >= n4) return;
    float4 v = reinterpret_cast<const float4*>(x)[i];
    __half2* yp = reinterpret_cast<__half2*>(y);
    yp[2*i]   = __floats2half2_rn(v.x, v.y);
    yp[2*i+1] = __floats2half2_rn(v.z, v.w);
}

// ---------------------------------------------------------------------------
// mma.sync fp16 NT GEMM. Tile 128x128, BK=64, 8 warps, 3-stage, 2 CTAs/SM.
// MODE 0: fp16 out. MODE 1: fp16 bias+elu+1. MODE 2: fp16 + bias. MODE 3: fp32 + bias.
// ---------------------------------------------------------------------------
#define BKC        64
#define RSTRIDE_B  144
#define A_TILE_BY  (128 * RSTRIDE_B)
#define B_TILE_BY  (128 * RSTRIDE_B)
#define STAGE_BY   (A_TILE_BY + B_TILE_BY)
#define NSTAGE     3
#define SMEM_GEMM  (NSTAGE * STAGE_BY)      // 110592
#define OFF_A      0
#define OFF_B      A_TILE_BY

__device__ __forceinline__ void load_stage_mma(
    uint32_t sb, int tid, int s, int k0,
    const __half* __restrict__ A, const __half* __restrict__ B,
    int K, int aRow0, int bRow0)
{
    const uint32_t stage = sb + (uint32_t)s * STAGE_BY;
#pragma unroll
    for (int i = 0; i < 8; ++i) {
        int idx = tid + i * 256;
        int row = (idx & 1023) >> 3;
        int cb  = idx & 7;
        const __half* gp;
        int r0;
        uint32_t tbase;
        if (idx < 1024) { gp = A; r0 = aRow0; tbase = OFF_A; }
        else            { gp = B; r0 = bRow0; tbase = OFF_B; }
        const void* ga = gp + (size_t)(r0 + row) * K + k0 + cb * 8;
        uint32_t so = stage + tbase + (uint32_t)row * RSTRIDE_B + cb * 16;
        CP_ASYNC16(so, ga);
    }
    CP_COMMIT();
}

template <int MODE>
__global__ __launch_bounds__(256, 2) void gemm_mma1(
    const __half* __restrict__ A, const __half* __restrict__ B,
    const float* __restrict__ bias, float* __restrict__ Cf,
    __half* __restrict__ Ch,
    int Nn, int K)
{
    extern __shared__ char smem[];
    const uint32_t sb = smem_u32(smem);
    const int tid = threadIdx.x;
    const int wid = tid >> 5;
    const int lane = tid & 31;
    const int bn = blockIdx.x, bm = blockIdx.y;
    const int warp_m = wid >> 2;
    const int warp_n = wid & 3;
    const int aRow0 = bm * 128, bRow0 = bn * 128;

    float acc[4][4][4];
#pragma unroll
    for (int mt = 0; mt < 4; ++mt)
#pragma unroll
        for (int nt = 0; nt < 4; ++nt)
#pragma unroll
            for (int j = 0; j < 4; ++j) acc[mt][nt][j] = 0.f;

    const int nch = K / BKC;

    load_stage_mma(sb, tid, 0, 0,   A, B, K, aRow0, bRow0);
    load_stage_mma(sb, tid, 1, BKC, A, B, K, aRow0, bRow0);

    const int a_r = lane & 15;
    const int a_c = (lane >> 4) * 8;
    const int b_n = ((lane >> 4) << 3) + (lane & 7);
    const int b_k = ((lane >> 3) & 1) * 8;

    for (int c = 0; c < nch; ++c) {
        if (c == nch - 1) { CP_WAIT(0); } else { CP_WAIT(1); }
        __syncthreads();

        if (c + 2 < nch)
            load_stage_mma(sb, tid, (c + 2) % NSTAGE, (c + 2) * BKC,
                           A, B, K, aRow0, bRow0);

        const uint32_t st = sb + (uint32_t)(c % NSTAGE) * STAGE_BY;
#pragma unroll
        for (int ks = 0; ks < 4; ++ks) {
            const int k0 = ks * 16;
            uint32_t ar[4][4];
#pragma unroll
            for (int mt = 0; mt < 4; ++mt) {
                uint32_t off = (uint32_t)(warp_m * 64 + mt * 16 + a_r) * RSTRIDE_B
                             + (uint32_t)(k0 + a_c) * 2;
                ldsm4(ar[mt], st + OFF_A + off);
            }
            uint32_t br[4][2];
#pragma unroll
            for (int nt2 = 0; nt2 < 2; ++nt2) {
                uint32_t off = (uint32_t)(warp_n * 32 + nt2 * 16 + b_n) * RSTRIDE_B
                             + (uint32_t)(k0 + b_k) * 2;
                uint32_t t4[4];
                ldsm4(t4, st + OFF_B + off);
                br[nt2*2][0] = t4[0]; br[nt2*2][1] = t4[1];
                br[nt2*2+1][0] = t4[2]; br[nt2*2+1][1] = t4[3];
            }
#pragma unroll
            for (int mt = 0; mt < 4; ++mt)
#pragma unroll
                for (int nt = 0; nt < 4; ++nt)
                    mma16816(acc[mt][nt], ar[mt], br[nt]);
        }
    }

    // epilogue
#pragma unroll
    for (int mt = 0; mt < 4; ++mt) {
#pragma unroll
        for (int nt = 0; nt < 4; ++nt) {
            const int row0 = bm * 128 + warp_m * 64 + mt * 16 + (lane >> 2);
            const int col  = bn * 128 + warp_n * 32 + nt * 8 + (lane & 3) * 2;
#pragma unroll
            for (int h = 0; h < 2; ++h) {
                const int row = row0 + h * 8;
                float f0 = acc[mt][nt][h * 2 + 0];
                float f1 = acc[mt][nt][h * 2 + 1];
                if (MODE >= 1) {
                    f0 += __ldg(bias + col);
                    f1 += __ldg(bias + col + 1);
                }
                if (MODE == 1) {
                    f0 = (f0 > 0.f) ? (f0 + 1.f) : __expf(f0);
                    f1 = (f1 > 0.f) ? (f1 + 1.f) : __expf(f1);
                }
                if (MODE == 3) {
                    *reinterpret_cast<float2*>(Cf + (size_t)row * Nn + col) =
                        make_float2(f0, f1);
                } else {
                    *reinterpret_cast<__half2*>(Ch + (size_t)row * Nn + col) =
                        __floats2half2_rn(f0, f1);
                }
            }
        }
    }
}

// ---------------------------------------------------------------------------
// zero kernel
// ---------------------------------------------------------------------------
__global__ void zero_kernel(float* __restrict__ p, int n)
{
    int i = blockIdx.x * blockDim.x + threadIdx.x;
    if (i < n) p[i] = 0.f;
}

// ---------------------------------------------------------------------------
// kv via MMA: kv[bh][d][e] += sum_n k[n,d]*v[n,e]  (K^T V per head)
// grid (BH, 4): 2048 tokens per block, tiles of 64 tokens, 3-stage cp.async.
// 8 warps: warp_m = wid>>1 (d tile 16), warp_n = wid&1 (e tile 32).
// Both operands transposed in smem -> ldmatrix.trans.
// ---------------------------------------------------------------------------
#define KVNCH   4
#define KVTOK   (Nseq / KVNCH)     // 2048
#define KV_STR  144
#define KV_TILE (64 * KV_STR)      // 9216 per tile
#define KV_STG  (2 * KV_TILE)      // 18432 (k + v)

__global__ __launch_bounds__(256, 2) void kv_mma_kernel(
    const __half* __restrict__ KH, const __half* __restrict__ VH,
    float* __restrict__ kv)
{
    __shared__ char smem[3 * KV_STG];   // 55296
    const uint32_t sb = smem_u32(smem);

    const int bh = blockIdx.x;
    const int b = bh >> 4, h = bh & 15;
    const int chunk = blockIdx.y;
    const int tid = threadIdx.x;
    const int wid = tid >> 5;
    const int lane = tid & 31;
    const int warp_m = wid >> 1;        // 0..3, d tile of 16
    const int warp_n = wid & 1;         // 0..1, e tile of 32

    const size_t tokBase = (size_t)b * Nseq + (size_t)chunk * KVTOK;

    // ldmatrix.trans lane addressing
    // A (k^T): tiles a0=(d0-7,t0-7) a1=(d8-15,t0-7) a2=(d0-7,t8-15) a3=(d8-15,t8-15)
    const int atr = (lane & 7) + ((lane >> 4) << 3);     // token row
    const int atc = ((lane >> 3) & 1) * 16;              // d byte offset
    // B (v^T): tiles b0=(e0-7,t0-7) b1=(e0-7,t8-15) b2=(e8-15,t0-7) b3=(e8-15,t8-15)
    const int btr = (lane & 7) + ((lane >> 3) & 1) * 8;  // token row
    const int btc = (lane >> 4) * 16;                    // e byte offset

    float acc[4][4];
#pragma unroll
    for (int nt = 0; nt < 4; ++nt)
#pragma unroll
        for (int j = 0; j < 4; ++j) acc[nt][j] = 0.f;

    const int niter = KVTOK / 64;       // 32

    // loader: 64 rows x 8 chunks x 2 tiles = 1024 cp.async; 4 per thread
    auto load_tile = [&](int s, int it) {
        const uint32_t stage = sb + (uint32_t)s * KV_STG;
#pragma unroll
        for (int i = 0; i < 4; ++i) {
            int idx = tid + i * 256;
            int tile = idx >> 9;        // 0 = k, 1 = v
            int w = idx & 511;
            int row = w >> 3, cb = w & 7;
            const __half* gp = tile ? VH : KH;
            const void* ga = gp + (tokBase + (size_t)it * 64 + row) * EMBED + h * HDIM + cb * 8;
            uint32_t so = stage + (uint32_t)tile * KV_TILE + (uint32_t)row * KV_STR + cb * 16;
            CP_ASYNC16(so, ga);
        }
        CP_COMMIT();
    };

    load_tile(0, 0);
    load_tile(1, 1);

    for (int it = 0; it < niter; ++it) {
        if (it == niter - 1) { CP_WAIT(0); } else { CP_WAIT(1); }
        __syncthreads();

        if (it + 2 < niter)
            load_tile((it + 2) % 3, it + 2);

        const uint32_t st = sb + (uint32_t)(it % 3) * KV_STG;
        const uint32_t kb = st;
        const uint32_t vb = st + KV_TILE;

#pragma unroll
        for (int ts = 0; ts < 4; ++ts) {
            const int t0 = ts * 16;
            uint32_t a4[4];
            ldsm4t(a4, kb + (uint32_t)(t0 + atr) * KV_STR
                      + (uint32_t)(warp_m * 32) + atc);
            uint32_t br[4][2];
#pragma unroll
            for (int nt2 = 0; nt2 < 2; ++nt2) {
                uint32_t t4[4];
                ldsm4t(t4, vb + (uint32_t)(t0 + btr) * KV_STR
                          + (uint32_t)(warp_n * 64 + nt2 * 32) + btc);
                br[nt2*2][0]   = t4[0]; br[nt2*2][1]   = t4[1];
                br[nt2*2+1][0] = t4[2]; br[nt2*2+1][1] = t4[3];
            }
#pragma unroll
            for (int nt = 0; nt < 4; ++nt)
                mma16816(acc[nt], a4, br[nt]);
        }
    }

    // epilogue: atomicAdd into kv[bh][d][e]
    float* kvp = kv + (size_t)bh * (HDIM * HDIM);
#pragma unroll
    for (int nt = 0; nt < 4; ++nt) {
#pragma unroll
        for (int hh = 0; hh < 2; ++hh) {
            const int d = warp_m * 16 + (lane >> 2) + hh * 8;
            const int e = warp_n * 32 + nt * 8 + (lane & 3) * 2;
            atomicAdd(kvp + d * HDIM + e,     acc[nt][hh * 2 + 0]);
            atomicAdd(kvp + d * HDIM + e + 1, acc[nt][hh * 2 + 1]);
        }
    }
}

// ---------------------------------------------------------------------------
// ksum: column sums of KH.  ksum[bh][d] = sum_n KH[b,n,h*64+d]
// grid (EMBED/256, Bv, Nseq/1024); block 256
// ---------------------------------------------------------------------------
__global__ __launch_bounds__(256) void ksum_kernel(
    const __half* __restrict__ KH, float* __restrict__ ksum)
{
    const int col = blockIdx.x * 256 + threadIdx.x;
    const int b = blockIdx.y;
    const int n0 = blockIdx.z * 1024;
    const __half* p = KH + ((size_t)b * Nseq + n0) * EMBED + col;
    float s0 = 0.f, s1 = 0.f, s2 = 0.f, s3 = 0.f;
#pragma unroll 4
    for (int r = 0; r < 1024; r += 4) {
        s0 += __half2float(p[(size_t)(r + 0) * EMBED]);
        s1 += __half2float(p[(size_t)(r + 1) * EMBED]);
        s2 += __half2float(p[(size_t)(r + 2) * EMBED]);
        s3 += __half2float(p[(size_t)(r + 3) * EMBED]);
    }
    const int bh = b * 16 + (col >> 6);
    const int d = col & 63;
    atomicAdd(ksum + bh * 64 + d, (s0 + s1) + (s2 + s3));
}

// ---------------------------------------------------------------------------
// kvT convert: kv[bh][d][e] fp32 -> kvTh[bh][e][d] fp16
// ---------------------------------------------------------------------------
__global__ __launch_bounds__(256) void kvT_cvt_kernel(
    const float* __restrict__ kv, __half* __restrict__ kvTh)
{
    const int bh = blockIdx.x;
    const int tid = threadIdx.x;
    __shared__ float s[64][65];
    for (int i = tid; i < 4096; i += 256)
        s[i >> 6][i & 63] = kv[(size_t)bh * 4096 + i];
    __syncthreads();
    for (int i = tid; i < 4096; i += 256) {
        const int e = i >> 6, d = i & 63;
        kvTh[(size_t)bh * 4096 + i] = __float2half(s[d][e]);
    }
}

// ---------------------------------------------------------------------------
// denom: dinv[bh][n] = 1 / (q[bh,n,:].ksum[bh,:] + 1e-6)
// ---------------------------------------------------------------------------
__global__ __launch_bounds__(256) void denom_kernel(
    const __half* __restrict__ Qh, const float* __restrict__ ksum,
    float* __restrict__ dinv)
{
    const int bh = blockIdx.y;
    const int b = bh >> 4, h = bh & 15;
    const int tok = blockIdx.x * 256 + threadIdx.x;

    __shared__ float ks_s[64];
    if (threadIdx.x < 64) ks_s[threadIdx.x] = ksum[bh * 64 + threadIdx.x];
    __syncthreads();

    const __half2* qp = reinterpret_cast<const __half2*>(
        Qh + ((size_t)b * Nseq + tok) * EMBED + h * HDIM);
    float d = 0.f;
#pragma unroll
    for (int j = 0; j < 32; ++j) {
        float2 q2 = __half22float2(qp[j]);
        d = fmaf(q2.x, ks_s[2 * j], d);
        d = fmaf(q2.y, ks_s[2 * j + 1], d);
    }
    dinv[(size_t)bh * Nseq + tok] = 1.0f / (d + 1e-6f);
}

// ---------------------------------------------------------------------------
// attn numerator via MMA: atH = (Q @ kvT^T) * dinv
// ---------------------------------------------------------------------------
#define AT_STR 144
__global__ __launch_bounds__(256) void attn_mma_kernel(
    const __half* __restrict__ Qh, const __half* __restrict__ kvTh,
    const float* __restrict__ dinv, __half* __restrict__ atH)
{
    __shared__ char smem[128 * AT_STR + 64 * AT_STR];
    const uint32_t sq = smem_u32(smem);
    const uint32_t skt = sq + 128 * AT_STR;

    const int bh = blockIdx.x;
    const int b = bh >> 4, h = bh & 15;
    const int tt = blockIdx.y;
    const int tid = threadIdx.x;
    const int wid = tid >> 5;
    const int lane = tid & 31;
    const int warp_m = wid >> 1;
    const int warp_n = wid & 1;

#pragma unroll
    for (int i = 0; i < 4; ++i) {
        int idx = tid + i * 256;
        int row = idx >> 3, cb = idx & 7;
        const void* ga = Qh + ((size_t)b * Nseq + tt * 128 + row) * EMBED + h * HDIM + cb * 8;
        CP_ASYNC16(sq + (uint32_t)row * AT_STR + cb * 16, ga);
    }
#pragma unroll
    for (int i = 0; i < 2; ++i) {
        int idx = tid + i * 256;
        int row = idx >> 3, cb = idx & 7;
        const void* ga = kvTh + (size_t)bh * 4096 + row * 64 + cb * 8;
        CP_ASYNC16(skt + (uint32_t)row * AT_STR + cb * 16, ga);
    }
    CP_COMMIT();
    CP_WAIT(0);
    __syncthreads();

    const int a_r = lane & 15;
    const int a_c = (lane >> 4) * 8;
    const int b_n = ((lane >> 4) << 3) + (lane & 7);
    const int b_k = ((lane >> 3) & 1) * 8;

    float acc[2][4][4];
#pragma unroll
    for (int mt = 0; mt < 2; ++mt)
#pragma unroll
        for (int nt = 0; nt < 4; ++nt)
#pragma unroll
            for (int j = 0; j < 4; ++j) acc[mt][nt][j] = 0.f;

#pragma unroll
    for (int ks = 0; ks < 4; ++ks) {
        const int k0 = ks * 16;
        uint32_t ar[2][4];
#pragma unroll
        for (int mt = 0; mt < 2; ++mt) {
            uint32_t off = (uint32_t)(warp_m * 32 + mt * 16 + a_r) * AT_STR
                         + (uint32_t)(k0 + a_c) * 2;
            ldsm4(ar[mt], sq + off);
        }
        uint32_t br[4][2];
#pragma unroll
        for (int nt2 = 0; nt2 < 2; ++nt2) {
            uint32_t off = (uint32_t)(warp_n * 32 + nt2 * 16 + b_n) * AT_STR
                         + (uint32_t)(k0 + b_k) * 2;
            uint32_t t4[4];
            ldsm4(t4, skt + off);
            br[nt2*2][0] = t4[0]; br[nt2*2][1] = t4[1];
            br[nt2*2+1][0] = t4[2]; br[nt2*2+1][1] = t4[3];
        }
#pragma unroll
        for (int mt = 0; mt < 2; ++mt)
#pragma unroll
            for (int nt = 0; nt < 4; ++nt)
                mma16816(acc[mt][nt], ar[mt], br[nt]);
    }

#pragma unroll
    for (int mt = 0; mt < 2; ++mt) {
#pragma unroll
        for (int hh = 0; hh < 2; ++hh) {
            const int rloc = warp_m * 32 + mt * 16 + (lane >> 2) + hh * 8;
            const float dv = __ldg(dinv + (size_t)bh * Nseq + tt * 128 + rloc);
            const size_t ob = ((size_t)b * Nseq + tt * 128 + rloc) * EMBED + h * HDIM;
#pragma unroll
            for (int nt = 0; nt < 4; ++nt) {
                const int col = warp_n * 32 + nt * 8 + (lane & 3) * 2;
                float f0 = acc[mt][nt][hh * 2 + 0] * dv;
                float f1 = acc[mt][nt][hh * 2 + 1] * dv;
                *reinterpret_cast<__half2*>(atH + ob + col) = __floats2half2_rn(f0, f1);
            }
        }
    }
}

// ---------------------------------------------------------------------------
// launch
// ---------------------------------------------------------------------------
extern "C" void kernel_launch(void* const* d_in, const int* in_sizes, int n_in,
                              void* d_out, int out_size)
{
    const float* query   = (const float*)d_in[0];
    const float* key_    = (const float*)d_in[1];
    const float* value   = (const float*)d_in[2];
    const float* Wq_down = (const float*)d_in[3];
    const float* Wq_up   = (const float*)d_in[4];
    const float* bq_up   = (const float*)d_in[5];
    const float* Wk_down = (const float*)d_in[6];
    const float* Wk_up   = (const float*)d_in[7];
    const float* bk_up   = (const float*)d_in[8];
    const float* Wv_down = (const float*)d_in[9];
    const float* Wv_up   = (const float*)d_in[10];
    const float* bv_up   = (const float*)d_in[11];
    const float* Wo      = (const float*)d_in[12];
    const float* bo      = (const float*)d_in[13];
    float* out = (float*)d_out;

    __half *inH, *yH, *QH, *KH, *VH, *atH, *wH, *kvTh;
    float *KVKS, *DINV;
    cudaGetSymbolAddress((void**)&inH,  g_inH);
    cudaGetSymbolAddress((void**)&yH,   g_yH);
    cudaGetSymbolAddress((void**)&QH,   g_QH);
    cudaGetSymbolAddress((void**)&KH,   g_KH);
    cudaGetSymbolAddress((void**)&VH,   g_VH);
    cudaGetSymbolAddress((void**)&atH,  g_atH);
    cudaGetSymbolAddress((void**)&wH,   g_wH);
    cudaGetSymbolAddress((void**)&kvTh, g_kvTh);
    cudaGetSymbolAddress((void**)&KVKS, g_kvks);
    cudaGetSymbolAddress((void**)&DINV, g_dinv);
    float* KV = KVKS;
    float* KS = KVKS + KV_ELEMS;

    cudaFuncSetAttribute((const void*)gemm_mma1<0>, cudaFuncAttributeMaxDynamicSharedMemorySize, SMEM_GEMM);
    cudaFuncSetAttribute((const void*)gemm_mma1<1>, cudaFuncAttributeMaxDynamicSharedMemorySize, SMEM_GEMM);
    cudaFuncSetAttribute((const void*)gemm_mma1<2>, cudaFuncAttributeMaxDynamicSharedMemorySize, SMEM_GEMM);
    cudaFuncSetAttribute((const void*)gemm_mma1<3>, cudaFuncAttributeMaxDynamicSharedMemorySize, SMEM_GEMM);

    const dim3 blk(256);
    const dim3 gdown(RANK / 128, MTOK / 128);
    const dim3 gup(EMBED / 128, MTOK / 128);

    // weight converts
    cvt_kernel<<<(RANK*EMBED/4 + 255)/256, 256>>>(Wq_down, wH + W_QD, RANK*EMBED/4);
    cvt_kernel<<<(EMBED*RANK/4 + 255)/256, 256>>>(Wq_up,   wH + W_QU, EMBED*RANK/4);
    cvt_kernel<<<(RANK*EMBED/4 + 255)/256, 256>>>(Wk_down, wH + W_KD, RANK*EMBED/4);
    cvt_kernel<<<(EMBED*RANK/4 + 255)/256, 256>>>(Wk_up,   wH + W_KU, EMBED*RANK/4);
    cvt_kernel<<<(RANK*EMBED/4 + 255)/256, 256>>>(Wv_down, wH + W_VD, RANK*EMBED/4);
    cvt_kernel<<<(EMBED*RANK/4 + 255)/256, 256>>>(Wv_up,   wH + W_VU, EMBED*RANK/4);
    cvt_kernel<<<(EMBED*EMBED/4 + 255)/256, 256>>>(Wo,     wH + W_O,  EMBED*EMBED/4);

    const int nAct4 = MTOK * EMBED / 4;

    // Q path
    cvt_kernel<<<(nAct4 + 255)/256, 256>>>(query, inH, nAct4);
    gemm_mma1<0><<<gdown, blk, SMEM_GEMM>>>(inH, wH + W_QD, nullptr, nullptr, yH, RANK, EMBED);
    gemm_mma1<1><<<gup, blk, SMEM_GEMM>>>(yH, wH + W_QU, bq_up, nullptr, QH, EMBED, RANK);
    // K path
    cvt_kernel<<<(nAct4 + 255)/256, 256>>>(key_, inH, nAct4);
    gemm_mma1<0><<<gdown, blk, SMEM_GEMM>>>(inH, wH + W_KD, nullptr, nullptr, yH, RANK, EMBED);
    gemm_mma1<1><<<gup, blk, SMEM_GEMM>>>(yH, wH + W_KU, bk_up, nullptr, KH, EMBED, RANK);
    // V path
    cvt_kernel<<<(nAct4 + 255)/256, 256>>>(value, inH, nAct4);
    gemm_mma1<0><<<gdown, blk, SMEM_GEMM>>>(inH, wH + W_VD, nullptr, nullptr, yH, RANK, EMBED);
    gemm_mma1<2><<<gup, blk, SMEM_GEMM>>>(yH, wH + W_VU, bv_up, nullptr, VH, EMBED, RANK);

    // kv (MMA) / ksum
    const int nz = KV_ELEMS + KS_ELEMS;
    zero_kernel<<<(nz + 255) / 256, 256>>>(KVKS, nz);
    kv_mma_kernel<<<dim3(BH, KVNCH), dim3(256)>>>(KH, VH, KV);
    ksum_kernel<<<dim3(EMBED / 256, Bv, Nseq / 1024), dim3(256)>>>(KH, KS);
    kvT_cvt_kernel<<<BH, 256>>>(KV, kvTh);
    denom_kernel<<<dim3(Nseq / 256, BH), dim3(256)>>>(QH, KS, DINV);

    // attention numerator (MMA) + divide
    attn_mma_kernel<<<dim3(BH, Nseq / 128), dim3(256)>>>(QH, kvTh, DINV, atH);

    // output projection (fp32 out)
    gemm_mma1<3><<<gup, blk, SMEM_GEMM>>>(atH, wH + W_O, bo, out, nullptr, EMBED, EMBED);
}

// round 11
// speedup vs baseline: 6.5720x; 1.0551x over previous
#include <cuda_runtime.h>
#include <cuda_fp16.h>
#include <cstdint>

// ---------------------------------------------------------------------------
// Problem constants
// ---------------------------------------------------------------------------
#define Bv     4
#define Nseq   8192
#define EMBED  1024
#define HEADS  16
#define HDIM   64
#define RANK   512
#define MTOK   (Bv * Nseq)          // 32768
#define BH     (Bv * HEADS)         // 64

// ---------------------------------------------------------------------------
// Scratch (__device__ globals; allocation forbidden)
// ---------------------------------------------------------------------------
__device__ __half g_inH3[(size_t)3 * MTOK * EMBED];   // fp16 q/k/v inputs
__device__ __half g_yH3 [(size_t)3 * MTOK * RANK];    // low-rank intermediates
__device__ __half g_QH [MTOK * EMBED];
__device__ __half g_KH [MTOK * EMBED];
__device__ __half g_VH [MTOK * EMBED];
__device__ __half g_atH[MTOK * EMBED];

#define W_QD 0
#define W_QU (W_QD + RANK*EMBED)
#define W_KD (W_QU + EMBED*RANK)
#define W_KU (W_KD + RANK*EMBED)
#define W_VD (W_KU + EMBED*RANK)
#define W_VU (W_VD + RANK*EMBED)
#define W_O  (W_VU + EMBED*RANK)
#define W_TOT (W_O + EMBED*EMBED)
__device__ __half g_wH[W_TOT];

#define KV_ELEMS (BH * HDIM * HDIM)     // 262144
#define KS_ELEMS (BH * HDIM)            // 4096
__device__ float  g_kvks[KV_ELEMS + KS_ELEMS];
__device__ __half g_kvTh[KV_ELEMS];
__device__ float  g_dinv[BH * Nseq];

// ---------------------------------------------------------------------------
// helpers
// ---------------------------------------------------------------------------
__device__ __forceinline__ uint32_t smem_u32(const void* p) {
    uint32_t a;
    asm("{ .reg .u64 t; cvta.to.shared.u64 t, %1; cvt.u32.u64 %0, t; }"
        : "=r"(a) : "l"(p));
    return a;
}

__device__ __forceinline__ void ldsm4(uint32_t* r, uint32_t addr) {
    asm volatile("ldmatrix.sync.aligned.m8n8.x4.shared.b16 {%0,%1,%2,%3}, [%4];"
        : "=r"(r[0]), "=r"(r[1]), "=r"(r[2]), "=r"(r[3]) : "r"(addr));
}

__device__ __forceinline__ void ldsm4t(uint32_t* r, uint32_t addr) {
    asm volatile("ldmatrix.sync.aligned.m8n8.x4.trans.shared.b16 {%0,%1,%2,%3}, [%4];"
        : "=r"(r[0]), "=r"(r[1]), "=r"(r[2]), "=r"(r[3]) : "r"(addr));
}

__device__ __forceinline__ void mma16816(float* c, const uint32_t* a, const uint32_t* b) {
    asm volatile("mma.sync.aligned.m16n8k16.row.col.f32.f16.f16.f32 "
        "{%0,%1,%2,%3}, {%4,%5,%6,%7}, {%8,%9}, {%0,%1,%2,%3};"
        : "+f"(c[0]), "+f"(c[1]), "+f"(c[2]), "+f"(c[3])
        : "r"(a[0]), "r"(a[1]), "r"(a[2]), "r"(a[3]), "r"(b[0]), "r"(b[1]));
}

#define CP_ASYNC16(so, ga) \
    asm volatile("cp.async.cg.shared.global [%0], [%1], 16;\n" :: "r"(so), "l"(ga))
#define CP_COMMIT() asm volatile("cp.async.commit_group;\n" ::: "memory")
#define CP_WAIT(n)  asm volatile("cp.async.wait_group %0;\n" :: "n"(n) : "memory")

// ---------------------------------------------------------------------------
// cvt3: q/k/v fp32 -> fp16, one launch, z selects tensor. 8 elems/thread.
// ---------------------------------------------------------------------------
__global__ void cvt3_kernel(const float* __restrict__ x0,
                            const float* __restrict__ x1,
                            const float* __restrict__ x2)
{
    const int z = blockIdx.y;
    const float* x = (z == 0) ? x0 : (z == 1) ? x1 : x2;
    __half* dst = g_inH3 + (size_t)z * (MTOK * EMBED);
    const int i = blockIdx.x * 256 + threadIdx.x;       // group of 8 floats
    const float4* xp = reinterpret_cast<const float4*>(x) + 2 * (size_t)i;
    float4 a = xp[0], b = xp[1];
    __half2* yp = reinterpret_cast<__half2*>(dst) + 4 * (size_t)i;
    yp[0] = __floats2half2_rn(a.x, a.y);
    yp[1] = __floats2half2_rn(a.z, a.w);
    yp[2] = __floats2half2_rn(b.x, b.y);
    yp[3] = __floats2half2_rn(b.z, b.w);
}

// ---------------------------------------------------------------------------
// wcvt: all 7 weights fp32 -> fp16 in one launch. Segments are contiguous in
// g_wH in input order, all 524288 elems except Wo (1048576).
// ---------------------------------------------------------------------------
#define WSEG4 (RANK * EMBED / 4)            // 131072 float4 per small segment
__global__ void wcvt_kernel(const float* __restrict__ p0, const float* __restrict__ p1,
                            const float* __restrict__ p2, const float* __restrict__ p3,
                            const float* __restrict__ p4, const float* __restrict__ p5,
                            const float* __restrict__ p6)
{
    const int i = blockIdx.x * 256 + threadIdx.x;       // float4 index, < 1048576
    int seg, off;
    if (i >= 6 * WSEG4) { seg = 6; off = i - 6 * WSEG4; }
    else                { seg = i / WSEG4; off = i % WSEG4; }
    const float* ps[7] = {p0, p1, p2, p3, p4, p5, p6};
    float4 v = reinterpret_cast<const float4*>(ps[seg])[off];
    __half2* yp = reinterpret_cast<__half2*>(g_wH) + 2 * (size_t)i;
    yp[0] = __floats2half2_rn(v.x, v.y);
    yp[1] = __floats2half2_rn(v.z, v.w);
}

// ---------------------------------------------------------------------------
// fused mma.sync fp16 NT GEMM. Tile 128x128, BK=64, 8 warps, 3-stage, 2 CTA/SM.
// KIND 0: down3  (z picks q/k/v chain; fp16 out, no bias)
// KIND 1: up3    (z picks chain; fp16 out, bias; elu+1 for z<2)
// KIND 2: Wo     (fp32 out + bias)
// ---------------------------------------------------------------------------
#define BKC        64
#define RSTRIDE_B  144
#define A_TILE_BY  (128 * RSTRIDE_B)
#define B_TILE_BY  (128 * RSTRIDE_B)
#define STAGE_BY   (A_TILE_BY + B_TILE_BY)
#define NSTAGE     3
#define SMEM_GEMM  (NSTAGE * STAGE_BY)      // 110592
#define OFF_A      0
#define OFF_B      A_TILE_BY

__device__ __forceinline__ void load_stage_mma(
    uint32_t sb, int tid, int s, int k0,
    const __half* __restrict__ A, const __half* __restrict__ B,
    int K, int aRow0, int bRow0)
{
    const uint32_t stage = sb + (uint32_t)s * STAGE_BY;
#pragma unroll
    for (int i = 0; i < 8; ++i) {
        int idx = tid + i * 256;
        int row = (idx & 1023) >> 3;
        int cb  = idx & 7;
        const __half* gp;
        int r0;
        uint32_t tbase;
        if (idx < 1024) { gp = A; r0 = aRow0; tbase = OFF_A; }
        else            { gp = B; r0 = bRow0; tbase = OFF_B; }
        const void* ga = gp + (size_t)(r0 + row) * K + k0 + cb * 8;
        uint32_t so = stage + tbase + (uint32_t)row * RSTRIDE_B + cb * 16;
        CP_ASYNC16(so, ga);
    }
    CP_COMMIT();
}

template <int KIND>
__global__ __launch_bounds__(256, 2) void gemm_fused(
    const float* __restrict__ b0, const float* __restrict__ b1,
    const float* __restrict__ b2, float* __restrict__ outF)
{
    constexpr int NN = (KIND == 0) ? RANK : EMBED;
    constexpr int KK = (KIND == 0) ? EMBED : ((KIND == 1) ? RANK : EMBED);

    extern __shared__ char smem[];
    const uint32_t sb = smem_u32(smem);
    const int tid = threadIdx.x;
    const int wid = tid >> 5;
    const int lane = tid & 31;
    const int bn = blockIdx.x, bm = blockIdx.y;
    const int z = (KIND == 2) ? 0 : blockIdx.z;
    const int warp_m = wid >> 2;
    const int warp_n = wid & 3;
    const int aRow0 = bm * 128, bRow0 = bn * 128;

    const __half* A;
    const __half* B;
    __half* Ch = nullptr;
    const float* bias = nullptr;
    bool elu = false;
    if (KIND == 0) {
        A = g_inH3 + (size_t)z * (MTOK * EMBED);
        B = g_wH + (size_t)z * (2 * RANK * EMBED);          // W_QD/W_KD/W_VD
        Ch = g_yH3 + (size_t)z * (MTOK * RANK);
    } else if (KIND == 1) {
        A = g_yH3 + (size_t)z * (MTOK * RANK);
        B = g_wH + W_QU + (size_t)z * (2 * RANK * EMBED);   // W_QU/W_KU/W_VU
        bias = (z == 0) ? b0 : (z == 1) ? b1 : b2;
        Ch = (z == 0) ? g_QH : (z == 1) ? g_KH : g_VH;
        elu = (z < 2);
    } else {
        A = g_atH;
        B = g_wH + W_O;
        bias = b0;
    }

    float acc[4][4][4];
#pragma unroll
    for (int mt = 0; mt < 4; ++mt)
#pragma unroll
        for (int nt = 0; nt < 4; ++nt)
#pragma unroll
            for (int j = 0; j < 4; ++j) acc[mt][nt][j] = 0.f;

    const int nch = KK / BKC;

    load_stage_mma(sb, tid, 0, 0,   A, B, KK, aRow0, bRow0);
    load_stage_mma(sb, tid, 1, BKC, A, B, KK, aRow0, bRow0);

    const int a_r = lane & 15;
    const int a_c = (lane >> 4) * 8;
    const int b_n = ((lane >> 4) << 3) + (lane & 7);
    const int b_k = ((lane >> 3) & 1) * 8;

    for (int c = 0; c < nch; ++c) {
        if (c == nch - 1) { CP_WAIT(0); } else { CP_WAIT(1); }
        __syncthreads();

        if (c + 2 < nch)
            load_stage_mma(sb, tid, (c + 2) % NSTAGE, (c + 2) * BKC,
                           A, B, KK, aRow0, bRow0);

        const uint32_t st = sb + (uint32_t)(c % NSTAGE) * STAGE_BY;
#pragma unroll
        for (int ks = 0; ks < 4; ++ks) {
            const int k0 = ks * 16;
            uint32_t ar[4][4];
#pragma unroll
            for (int mt = 0; mt < 4; ++mt) {
                uint32_t off = (uint32_t)(warp_m * 64 + mt * 16 + a_r) * RSTRIDE_B
                             + (uint32_t)(k0 + a_c) * 2;
                ldsm4(ar[mt], st + OFF_A + off);
            }
            uint32_t br[4][2];
#pragma unroll
            for (int nt2 = 0; nt2 < 2; ++nt2) {
                uint32_t off = (uint32_t)(warp_n * 32 + nt2 * 16 + b_n) * RSTRIDE_B
                             + (uint32_t)(k0 + b_k) * 2;
                uint32_t t4[4];
                ldsm4(t4, st + OFF_B + off);
                br[nt2*2][0] = t4[0]; br[nt2*2][1] = t4[1];
                br[nt2*2+1][0] = t4[2]; br[nt2*2+1][1] = t4[3];
            }
#pragma unroll
            for (int mt = 0; mt < 4; ++mt)
#pragma unroll
                for (int nt = 0; nt < 4; ++nt)
                    mma16816(acc[mt][nt], ar[mt], br[nt]);
        }
    }

    // epilogue
#pragma unroll
    for (int mt = 0; mt < 4; ++mt) {
#pragma unroll
        for (int nt = 0; nt < 4; ++nt) {
            const int row0 = bm * 128 + warp_m * 64 + mt * 16 + (lane >> 2);
            const int col  = bn * 128 + warp_n * 32 + nt * 8 + (lane & 3) * 2;
#pragma unroll
            for (int h = 0; h < 2; ++h) {
                const int row = row0 + h * 8;
                float f0 = acc[mt][nt][h * 2 + 0];
                float f1 = acc[mt][nt][h * 2 + 1];
                if (KIND >= 1) {
                    f0 += __ldg(bias + col);
                    f1 += __ldg(bias + col + 1);
                }
                if (KIND == 1 && elu) {
                    f0 = (f0 > 0.f) ? (f0 + 1.f) : __expf(f0);
                    f1 = (f1 > 0.f) ? (f1 + 1.f) : __expf(f1);
                }
                if (KIND == 2) {
                    *reinterpret_cast<float2*>(outF + (size_t)row * NN + col) =
                        make_float2(f0, f1);
                } else {
                    *reinterpret_cast<__half2*>(Ch + (size_t)row * NN + col) =
                        __floats2half2_rn(f0, f1);
                }
            }
        }
    }
}

// ---------------------------------------------------------------------------
// zero kernel
// ---------------------------------------------------------------------------
__global__ void zero_kernel(float* __restrict__ p, int n)
{
    int i = blockIdx.x * blockDim.x + threadIdx.x;
    if (i < n) p[i] = 0.f;
}

// ---------------------------------------------------------------------------
// kv via MMA: kv[bh][d][e] += sum_n k[n,d]*v[n,e]  (K^T V per head)
// ---------------------------------------------------------------------------
#define KVNCH   4
#define KVTOK   (Nseq / KVNCH)     // 2048
#define KV_STR  144
#define KV_TILE (64 * KV_STR)
#define KV_STG  (2 * KV_TILE)

__global__ __launch_bounds__(256, 2) void kv_mma_kernel(
    const __half* __restrict__ KH, const __half* __restrict__ VH,
    float* __restrict__ kv)
{
    __shared__ char smem[3 * KV_STG];
    const uint32_t sb = smem_u32(smem);

    const int bh = blockIdx.x;
    const int b = bh >> 4, h = bh & 15;
    const int chunk = blockIdx.y;
    const int tid = threadIdx.x;
    const int wid = tid >> 5;
    const int lane = tid & 31;
    const int warp_m = wid >> 1;
    const int warp_n = wid & 1;

    const size_t tokBase = (size_t)b * Nseq + (size_t)chunk * KVTOK;

    const int atr = (lane & 7) + ((lane >> 4) << 3);
    const int atc = ((lane >> 3) & 1) * 16;
    const int btr = (lane & 7) + ((lane >> 3) & 1) * 8;
    const int btc = (lane >> 4) * 16;

    float acc[4][4];
#pragma unroll
    for (int nt = 0; nt < 4; ++nt)
#pragma unroll
        for (int j = 0; j < 4; ++j) acc[nt][j] = 0.f;

    const int niter = KVTOK / 64;

    auto load_tile = [&](int s, int it) {
        const uint32_t stage = sb + (uint32_t)s * KV_STG;
#pragma unroll
        for (int i = 0; i < 4; ++i) {
            int idx = tid + i * 256;
            int tile = idx >> 9;
            int w = idx & 511;
            int row = w >> 3, cb = w & 7;
            const __half* gp = tile ? VH : KH;
            const void* ga = gp + (tokBase + (size_t)it * 64 + row) * EMBED + h * HDIM + cb * 8;
            uint32_t so = stage + (uint32_t)tile * KV_TILE + (uint32_t)row * KV_STR + cb * 16;
            CP_ASYNC16(so, ga);
        }
        CP_COMMIT();
    };

    load_tile(0, 0);
    load_tile(1, 1);

    for (int it = 0; it < niter; ++it) {
        if (it == niter - 1) { CP_WAIT(0); } else { CP_WAIT(1); }
        __syncthreads();

        if (it + 2 < niter)
            load_tile((it + 2) % 3, it + 2);

        const uint32_t st = sb + (uint32_t)(it % 3) * KV_STG;
        const uint32_t kb = st;
        const uint32_t vb = st + KV_TILE;

#pragma unroll
        for (int ts = 0; ts < 4; ++ts) {
            const int t0 = ts * 16;
            uint32_t a4[4];
            ldsm4t(a4, kb + (uint32_t)(t0 + atr) * KV_STR
                      + (uint32_t)(warp_m * 32) + atc);
            uint32_t br[4][2];
#pragma unroll
            for (int nt2 = 0; nt2 < 2; ++nt2) {
                uint32_t t4[4];
                ldsm4t(t4, vb + (uint32_t)(t0 + btr) * KV_STR
                          + (uint32_t)(warp_n * 64 + nt2 * 32) + btc);
                br[nt2*2][0]   = t4[0]; br[nt2*2][1]   = t4[1];
                br[nt2*2+1][0] = t4[2]; br[nt2*2+1][1] = t4[3];
            }
#pragma unroll
            for (int nt = 0; nt < 4; ++nt)
                mma16816(acc[nt], a4, br[nt]);
        }
    }

    float* kvp = kv + (size_t)bh * (HDIM * HDIM);
#pragma unroll
    for (int nt = 0; nt < 4; ++nt) {
#pragma unroll
        for (int hh = 0; hh < 2; ++hh) {
            const int d = warp_m * 16 + (lane >> 2) + hh * 8;
            const int e = warp_n * 32 + nt * 8 + (lane & 3) * 2;
            atomicAdd(kvp + d * HDIM + e,     acc[nt][hh * 2 + 0]);
            atomicAdd(kvp + d * HDIM + e + 1, acc[nt][hh * 2 + 1]);
        }
    }
}

// ---------------------------------------------------------------------------
// ksum: column sums of KH
// ---------------------------------------------------------------------------
__global__ __launch_bounds__(256) void ksum_kernel(
    const __half* __restrict__ KH, float* __restrict__ ksum)
{
    const int col = blockIdx.x * 256 + threadIdx.x;
    const int b = blockIdx.y;
    const int n0 = blockIdx.z * 1024;
    const __half* p = KH + ((size_t)b * Nseq + n0) * EMBED + col;
    float s0 = 0.f, s1 = 0.f, s2 = 0.f, s3 = 0.f;
#pragma unroll 4
    for (int r = 0; r < 1024; r += 4) {
        s0 += __half2float(p[(size_t)(r + 0) * EMBED]);
        s1 += __half2float(p[(size_t)(r + 1) * EMBED]);
        s2 += __half2float(p[(size_t)(r + 2) * EMBED]);
        s3 += __half2float(p[(size_t)(r + 3) * EMBED]);
    }
    const int bh = b * 16 + (col >> 6);
    const int d = col & 63;
    atomicAdd(ksum + bh * 64 + d, (s0 + s1) + (s2 + s3));
}

// ---------------------------------------------------------------------------
// kvT convert: kv[bh][d][e] fp32 -> kvTh[bh][e][d] fp16
// ---------------------------------------------------------------------------
__global__ __launch_bounds__(256) void kvT_cvt_kernel(
    const float* __restrict__ kv, __half* __restrict__ kvTh)
{
    const int bh = blockIdx.x;
    const int tid = threadIdx.x;
    __shared__ float s[64][65];
    for (int i = tid; i < 4096; i += 256)
        s[i >> 6][i & 63] = kv[(size_t)bh * 4096 + i];
    __syncthreads();
    for (int i = tid; i < 4096; i += 256) {
        const int e = i >> 6, d = i & 63;
        kvTh[(size_t)bh * 4096 + i] = __float2half(s[d][e]);
    }
}

// ---------------------------------------------------------------------------
// denom: dinv[bh][n] = 1 / (q . ksum + 1e-6)
// ---------------------------------------------------------------------------
__global__ __launch_bounds__(256) void denom_kernel(
    const __half* __restrict__ Qh, const float* __restrict__ ksum,
    float* __restrict__ dinv)
{
    const int bh = blockIdx.y;
    const int b = bh >> 4, h = bh & 15;
    const int tok = blockIdx.x * 256 + threadIdx.x;

    __shared__ float ks_s[64];
    if (threadIdx.x < 64) ks_s[threadIdx.x] = ksum[bh * 64 + threadIdx.x];
    __syncthreads();

    const __half2* qp = reinterpret_cast<const __half2*>(
        Qh + ((size_t)b * Nseq + tok) * EMBED + h * HDIM);
    float d = 0.f;
#pragma unroll
    for (int j = 0; j < 32; ++j) {
        float2 q2 = __half22float2(qp[j]);
        d = fmaf(q2.x, ks_s[2 * j], d);
        d = fmaf(q2.y, ks_s[2 * j + 1], d);
    }
    dinv[(size_t)bh * Nseq + tok] = 1.0f / (d + 1e-6f);
}

// ---------------------------------------------------------------------------
// attn numerator via MMA: atH = (Q @ kvT^T) * dinv
// ---------------------------------------------------------------------------
#define AT_STR 144
__global__ __launch_bounds__(256) void attn_mma_kernel(
    const __half* __restrict__ Qh, const __half* __restrict__ kvTh,
    const float* __restrict__ dinv, __half* __restrict__ atH)
{
    __shared__ char smem[128 * AT_STR + 64 * AT_STR];
    const uint32_t sq = smem_u32(smem);
    const uint32_t skt = sq + 128 * AT_STR;

    const int bh = blockIdx.x;
    const int b = bh >> 4, h = bh & 15;
    const int tt = blockIdx.y;
    const int tid = threadIdx.x;
    const int wid = tid >> 5;
    const int lane = tid & 31;
    const int warp_m = wid >> 1;
    const int warp_n = wid & 1;

#pragma unroll
    for (int i = 0; i < 4; ++i) {
        int idx = tid + i * 256;
        int row = idx >> 3, cb = idx & 7;
        const void* ga = Qh + ((size_t)b * Nseq + tt * 128 + row) * EMBED + h * HDIM + cb * 8;
        CP_ASYNC16(sq + (uint32_t)row * AT_STR + cb * 16, ga);
    }
#pragma unroll
    for (int i = 0; i < 2; ++i) {
        int idx = tid + i * 256;
        int row = idx >> 3, cb = idx & 7;
        const void* ga = kvTh + (size_t)bh * 4096 + row * 64 + cb * 8;
        CP_ASYNC16(skt + (uint32_t)row * AT_STR + cb * 16, ga);
    }
    CP_COMMIT();
    CP_WAIT(0);
    __syncthreads();

    const int a_r = lane & 15;
    const int a_c = (lane >> 4) * 8;
    const int b_n = ((lane >> 4) << 3) + (lane & 7);
    const int b_k = ((lane >> 3) & 1) * 8;

    float acc[2][4][4];
#pragma unroll
    for (int mt = 0; mt < 2; ++mt)
#pragma unroll
        for (int nt = 0; nt < 4; ++nt)
#pragma unroll
            for (int j = 0; j < 4; ++j) acc[mt][nt][j] = 0.f;

#pragma unroll
    for (int ks = 0; ks < 4; ++ks) {
        const int k0 = ks * 16;
        uint32_t ar[2][4];
#pragma unroll
        for (int mt = 0; mt < 2; ++mt) {
            uint32_t off = (uint32_t)(warp_m * 32 + mt * 16 + a_r) * AT_STR
                         + (uint32_t)(k0 + a_c) * 2;
            ldsm4(ar[mt], sq + off);
        }
        uint32_t br[4][2];
#pragma unroll
        for (int nt2 = 0; nt2 < 2; ++nt2) {
            uint32_t off = (uint32_t)(warp_n * 32 + nt2 * 16 + b_n) * AT_STR
                         + (uint32_t)(k0 + b_k) * 2;
            uint32_t t4[4];
            ldsm4(t4, skt + off);
            br[nt2*2][0] = t4[0]; br[nt2*2][1] = t4[1];
            br[nt2*2+1][0] = t4[2]; br[nt2*2+1][1] = t4[3];
        }
#pragma unroll
        for (int mt = 0; mt < 2; ++mt)
#pragma unroll
            for (int nt = 0; nt < 4; ++nt)
                mma16816(acc[mt][nt], ar[mt], br[nt]);
    }

#pragma unroll
    for (int mt = 0; mt < 2; ++mt) {
#pragma unroll
        for (int hh = 0; hh < 2; ++hh) {
            const int rloc = warp_m * 32 + mt * 16 + (lane >> 2) + hh * 8;
            const float dv = __ldg(dinv + (size_t)bh * Nseq + tt * 128 + rloc);
            const size_t ob = ((size_t)b * Nseq + tt * 128 + rloc) * EMBED + h * HDIM;
#pragma unroll
            for (int nt = 0; nt < 4; ++nt) {
                const int col = warp_n * 32 + nt * 8 + (lane & 3) * 2;
                float f0 = acc[mt][nt][hh * 2 + 0] * dv;
                float f1 = acc[mt][nt][hh * 2 + 1] * dv;
                *reinterpret_cast<__half2*>(atH + ob + col) = __floats2half2_rn(f0, f1);
            }
        }
    }
}

// ---------------------------------------------------------------------------
// launch
// ---------------------------------------------------------------------------
extern "C" void kernel_launch(void* const* d_in, const int* in_sizes, int n_in,
                              void* d_out, int out_size)
{
    const float* query   = (const float*)d_in[0];
    const float* key_    = (const float*)d_in[1];
    const float* value   = (const float*)d_in[2];
    const float* Wq_down = (const float*)d_in[3];
    const float* Wq_up   = (const float*)d_in[4];
    const float* bq_up   = (const float*)d_in[5];
    const float* Wk_down = (const float*)d_in[6];
    const float* Wk_up   = (const float*)d_in[7];
    const float* bk_up   = (const float*)d_in[8];
    const float* Wv_down = (const float*)d_in[9];
    const float* Wv_up   = (const float*)d_in[10];
    const float* bv_up   = (const float*)d_in[11];
    const float* Wo      = (const float*)d_in[12];
    const float* bo      = (const float*)d_in[13];
    float* out = (float*)d_out;

    __half *QH, *KH, *VH, *atH, *kvTh;
    float *KVKS, *DINV;
    cudaGetSymbolAddress((void**)&QH,   g_QH);
    cudaGetSymbolAddress((void**)&KH,   g_KH);
    cudaGetSymbolAddress((void**)&VH,   g_VH);
    cudaGetSymbolAddress((void**)&atH,  g_atH);
    cudaGetSymbolAddress((void**)&kvTh, g_kvTh);
    cudaGetSymbolAddress((void**)&KVKS, g_kvks);
    cudaGetSymbolAddress((void**)&DINV, g_dinv);
    float* KV = KVKS;
    float* KS = KVKS + KV_ELEMS;

    cudaFuncSetAttribute((const void*)gemm_fused<0>, cudaFuncAttributeMaxDynamicSharedMemorySize, SMEM_GEMM);
    cudaFuncSetAttribute((const void*)gemm_fused<1>, cudaFuncAttributeMaxDynamicSharedMemorySize, SMEM_GEMM);
    cudaFuncSetAttribute((const void*)gemm_fused<2>, cudaFuncAttributeMaxDynamicSharedMemorySize, SMEM_GEMM);

    const dim3 blk(256);

    // converts (2 launches)
    wcvt_kernel<<<(6 * WSEG4 + EMBED*EMBED/4 + 255) / 256, blk>>>(
        Wq_down, Wq_up, Wk_down, Wk_up, Wv_down, Wv_up, Wo);
    cvt3_kernel<<<dim3(MTOK * EMBED / 8 / 256, 3), blk>>>(query, key_, value);

    // down projections (one launch, z = q/k/v)
    gemm_fused<0><<<dim3(RANK / 128, MTOK / 128, 3), blk, SMEM_GEMM>>>(
        nullptr, nullptr, nullptr, nullptr);
    // up projections (one launch, z = q/k/v; elu for q,k)
    gemm_fused<1><<<dim3(EMBED / 128, MTOK / 128, 3), blk, SMEM_GEMM>>>(
        bq_up, bk_up, bv_up, nullptr);

    // kv (MMA) / ksum
    const int nz = KV_ELEMS + KS_ELEMS;
    zero_kernel<<<(nz + 255) / 256, blk>>>(KVKS, nz);
    kv_mma_kernel<<<dim3(BH, KVNCH), blk>>>(KH, VH, KV);
    ksum_kernel<<<dim3(EMBED / 256, Bv, Nseq / 1024), blk>>>(KH, KS);
    kvT_cvt_kernel<<<BH, blk>>>(KV, kvTh);
    denom_kernel<<<dim3(Nseq / 256, BH), blk>>>(QH, KS, DINV);

    // attention numerator (MMA) + divide
    attn_mma_kernel<<<dim3(BH, Nseq / 128), blk>>>(QH, kvTh, DINV, atH);

    // output projection (fp32 out)
    gemm_fused<2><<<dim3(EMBED / 128, MTOK / 128, 1), blk, SMEM_GEMM>>>(
        bo, nullptr, nullptr, out);
}